// round 11
// baseline (speedup 1.0000x reference)
#include <cuda_runtime.h>
#include <cuda_fp16.h>
#include <math.h>
#include <stdint.h>

#define D_MODEL 1024
#define NHEADS  16
#define HD      64
#define SEQ     2048
#define BATCH   2
#define WIN     256

// Scratch (allocation-free: __device__ globals). All fp16.
__device__ __half g_Q[BATCH * NHEADS * SEQ * HD];   // [b][h][l][d]
__device__ __half g_K[BATCH * NHEADS * SEQ * HD];
__device__ __half g_V[BATCH * NHEADS * SEQ * HD];
__device__ __half g_O[BATCH * SEQ * D_MODEL];       // [b][l][h*64+d]
__device__ __half c_x [BATCH * SEQ * D_MODEL];
__device__ __half c_w1[3 * D_MODEL * D_MODEL];
__device__ __half c_w2[D_MODEL * D_MODEL];

__device__ __forceinline__ void mma_f16(float c[4], const unsigned a[4], const unsigned b[2]) {
    asm volatile(
        "mma.sync.aligned.m16n8k16.row.col.f32.f16.f16.f32 "
        "{%0,%1,%2,%3}, {%4,%5,%6,%7}, {%8,%9}, {%0,%1,%2,%3};\n"
        : "+f"(c[0]), "+f"(c[1]), "+f"(c[2]), "+f"(c[3])
        : "r"(a[0]), "r"(a[1]), "r"(a[2]), "r"(a[3]),
          "r"(b[0]), "r"(b[1]));
}

__device__ __forceinline__ void ldsm_x4(unsigned a[4], unsigned saddr) {
    asm volatile("ldmatrix.sync.aligned.m8n8.x4.shared.b16 {%0,%1,%2,%3}, [%4];"
        : "=r"(a[0]), "=r"(a[1]), "=r"(a[2]), "=r"(a[3]) : "r"(saddr));
}

// ---------------------------------------------------------------------------
// fp32 -> fp16 bulk converter
// ---------------------------------------------------------------------------
__global__ void cvt_f16(const float4* __restrict__ in, uint2* __restrict__ out, int n4)
{
    int i = blockIdx.x * blockDim.x + threadIdx.x;
    if (i < n4) {
        float4 v = in[i];
        __half2 h01 = __floats2half2_rn(v.x, v.y);
        __half2 h23 = __floats2half2_rn(v.z, v.w);
        uint2 u;
        u.x = *(unsigned*)&h01;
        u.y = *(unsigned*)&h23;
        out[i] = u;
    }
}

// ---------------------------------------------------------------------------
// FP16 NT GEMM (fp32 accum), BK=64, 3-stage cp.async pipeline + ldmatrix.
// 512 threads (16 warps, 4x4), warp tile 32x32 -> 32 acc regs/thread,
// <=64 regs total => 2 CTAs/SM => occ 50% (was 22.5%).
// ---------------------------------------------------------------------------
#define SSTR 72
#define BK   64
#define STG_HALVES (128 * SSTR)
#define STG_BYTES  (STG_HALVES * 2)
#define NSTG 3

template <int MODE>
__global__ __launch_bounds__(512, 2)
void gemm_f16(const __half* __restrict__ A, const __half* __restrict__ W,
              const float* __restrict__ bias, float* __restrict__ Cout,
              int M, int N, int K)
{
    extern __shared__ __half sh[];
    __half* AsBase = sh;
    __half* BsBase = sh + NSTG * STG_HALVES;

    const __half* Ap = (MODE == 1) ? (const __half*)g_O : A;

    int tid  = threadIdx.x;
    int lane = tid & 31;
    int wid  = tid >> 5;               // 0..15
    int wm = (wid >> 2) * 32;          // 0,32,64,96
    int wn = (wid & 3) * 32;           // 0,32,64,96
    int bm = blockIdx.y * 128;
    int bn = blockIdx.x * 128;
    int g = lane >> 2;
    int t = lane & 3;
    int lr = lane & 7;

    int a_off = (wm + lr + (((lane >> 3) & 1) ? 8 : 0)) * SSTR + ((lane >> 4) ? 8 : 0);
    int b_off = (wn + lr + ((lane >> 4) ? 8 : 0)) * SSTR + (((lane >> 3) & 1) ? 8 : 0);

    unsigned shA = (unsigned)__cvta_generic_to_shared(AsBase);
    unsigned shB = (unsigned)__cvta_generic_to_shared(BsBase);

    float acc[2][4][4];
#pragma unroll
    for (int mt = 0; mt < 2; mt++)
#pragma unroll
        for (int nt = 0; nt < 4; nt++)
#pragma unroll
            for (int i = 0; i < 4; i++) acc[mt][nt][i] = 0.f;

    // Per tile per operand: 128 rows x 8 chunks(16B) = 1024 chunks; 512 thr -> 2 each
    auto issue = [&](int s, int k0) {
        __half* dA = AsBase + s * STG_HALVES;
        __half* dB = BsBase + s * STG_HALVES;
#pragma unroll
        for (int r = 0; r < 2; r++) {
            int id  = tid + r * 512;
            int row = id >> 3;
            int c   = id & 7;
            const __half* ga = Ap + (size_t)(bm + row) * K + k0 + c * 8;
            const __half* gb = W  + (size_t)(bn + row) * K + k0 + c * 8;
            unsigned sa = (unsigned)__cvta_generic_to_shared(dA + row * SSTR + c * 8);
            unsigned sb = (unsigned)__cvta_generic_to_shared(dB + row * SSTR + c * 8);
            asm volatile("cp.async.cg.shared.global [%0], [%1], 16;\n" :: "r"(sa), "l"(ga));
            asm volatile("cp.async.cg.shared.global [%0], [%1], 16;\n" :: "r"(sb), "l"(gb));
        }
        asm volatile("cp.async.commit_group;\n");
    };

    const int TILES = K / BK;
    issue(0, 0);
    issue(1, BK);

    int stage = 0, fill = 2;

    for (int t2 = 0; t2 < TILES; t2++) {
        asm volatile("cp.async.wait_group 1;\n" ::: "memory");
        __syncthreads();

        if (t2 + 2 < TILES) issue(fill, (t2 + 2) * BK);

        unsigned stA = shA + stage * STG_BYTES;
        unsigned stB = shB + stage * STG_BYTES;

#pragma unroll
        for (int ks = 0; ks < 4; ks++) {
            int kk = ks * 16;
            unsigned af[2][4], bf[2][4];
#pragma unroll
            for (int mt = 0; mt < 2; mt++)
                ldsm_x4(af[mt], stA + (unsigned)(a_off + mt * 16 * SSTR + kk) * 2);
#pragma unroll
            for (int p = 0; p < 2; p++)
                ldsm_x4(bf[p], stB + (unsigned)(b_off + p * 16 * SSTR + kk) * 2);
#pragma unroll
            for (int mt = 0; mt < 2; mt++)
#pragma unroll
                for (int nt = 0; nt < 4; nt++)
                    mma_f16(acc[mt][nt], af[mt], &bf[nt >> 1][(nt & 1) * 2]);
        }

        fill  = stage;
        stage = (stage == 2) ? 0 : stage + 1;
    }

#pragma unroll
    for (int mt = 0; mt < 2; mt++) {
#pragma unroll
        for (int nt = 0; nt < 4; nt++) {
#pragma unroll
            for (int i = 0; i < 4; i++) {
                int m = bm + wm + mt * 16 + g + ((i >> 1) ? 8 : 0);
                int n = bn + wn + nt * 8 + t * 2 + (i & 1);
                float v = acc[mt][nt][i] + bias[n];
                if (MODE == 0) {
                    int part   = n >> 10;
                    int within = n & 1023;
                    int h = within >> 6;
                    int d = within & 63;
                    int b = m >> 11;
                    int l = m & 2047;
                    size_t dst = ((size_t)(b * NHEADS + h) * SEQ + l) * HD + d;
                    __half* base = (part == 0) ? g_Q : (part == 1) ? g_K : g_V;
                    base[dst] = __float2half_rn(v);
                } else {
                    Cout[(size_t)m * N + n] = v;
                }
            }
        }
    }
}

// ---------------------------------------------------------------------------
// Sliding-window attention, fp16 mma + ldmatrix (R9 version: Q-tile 64,
// 128 threads, 4 warps x 16 query rows).
// ---------------------------------------------------------------------------
#define AST 72

__global__ __launch_bounds__(128)
void attn_mma()
{
    extern __shared__ __half smh[];
    __half* Qs = smh;                 // [q][d]  64 x AST
    __half* Ks = smh + 64 * AST;      // [j][d]
    __half* Vt = smh + 2 * 64 * AST;  // [d][j]
    __half* Ps = smh + 3 * 64 * AST;  // [q][j]

    int tid  = threadIdx.x;
    int lane = tid & 31;
    int wid  = tid >> 5;
    int g = lane >> 2;
    int t = lane & 3;
    int lr = lane & 7;

    int bh = blockIdx.y;
    int i0 = blockIdx.x * 64;

    const __half* Qg = g_Q + (size_t)bh * SEQ * HD;
    const __half* Kg = g_K + (size_t)bh * SEQ * HD;
    const __half* Vg = g_V + (size_t)bh * SEQ * HD;

    int rbase = wid * 16;
    int a_off = (rbase + lr + (((lane >> 3) & 1) ? 8 : 0)) * AST + ((lane >> 4) ? 8 : 0);
    int b_off = (lr + ((lane >> 4) ? 8 : 0)) * AST + (((lane >> 3) & 1) ? 8 : 0);

    unsigned shQ = (unsigned)__cvta_generic_to_shared(Qs);
    unsigned shK = (unsigned)__cvta_generic_to_shared(Ks);
    unsigned shV = (unsigned)__cvta_generic_to_shared(Vt);
    unsigned shP = (unsigned)__cvta_generic_to_shared(Ps);

    {
        int q = tid >> 1, half_sel = tid & 1;
        const __half2 s2 = __floats2half2_rn(0.125f, 0.125f);
#pragma unroll
        for (int v = 0; v < 4; v++) {
            int c8 = half_sel * 32 + v * 8;
            uint2 raw = *(const uint2*)(Qg + (size_t)(i0 + q) * HD + c8);
            __half2 h0 = __hmul2(*(__half2*)&raw.x, s2);
            __half2 h1 = __hmul2(*(__half2*)&raw.y, s2);
            uint2 raw2 = *(const uint2*)(Qg + (size_t)(i0 + q) * HD + c8 + 4);
            __half2 h2 = __hmul2(*(__half2*)&raw2.x, s2);
            __half2 h3 = __hmul2(*(__half2*)&raw2.y, s2);
            __half* dst = Qs + q * AST + c8;
            *(__half2*)(dst)     = h0;
            *(__half2*)(dst + 2) = h1;
            *(__half2*)(dst + 4) = h2;
            *(__half2*)(dst + 6) = h3;
        }
    }

    int iq0 = i0 + rbase + g;
    int iq1 = iq0 + 8;

    float m0 = -1e30f, m1 = -1e30f, l0 = 0.f, l1 = 0.f;
    float oacc[8][4];
#pragma unroll
    for (int nt = 0; nt < 8; nt++)
#pragma unroll
        for (int i = 0; i < 4; i++) oacc[nt][i] = 0.f;

    int kv_lo = i0 - (WIN - 1);
    if (kv_lo < 0) kv_lo = 0;
    int cs0 = (kv_lo / 64) * 64;

    for (int cs = cs0; cs <= i0; cs += 64) {
        __syncthreads();
        {
            int j = tid >> 1, half_sel = tid & 1;
#pragma unroll
            for (int v = 0; v < 2; v++) {
                int c16 = half_sel * 32 + v * 16;
                uint4 kraw = *(const uint4*)(Kg + (size_t)(cs + j) * HD + c16);
                *(uint4*)(Ks + j * AST + c16) = kraw;
                uint4 kraw2 = *(const uint4*)(Kg + (size_t)(cs + j) * HD + c16 + 8);
                *(uint4*)(Ks + j * AST + c16 + 8) = kraw2;

                uint4 vraw = *(const uint4*)(Vg + (size_t)(cs + j) * HD + c16);
                const __half* vh = (const __half*)&vraw;
#pragma unroll
                for (int e = 0; e < 8; e++)
                    Vt[(c16 + e) * AST + j] = vh[e];
                uint4 vraw2 = *(const uint4*)(Vg + (size_t)(cs + j) * HD + c16 + 8);
                const __half* vh2 = (const __half*)&vraw2;
#pragma unroll
                for (int e = 0; e < 8; e++)
                    Vt[(c16 + 8 + e) * AST + j] = vh2[e];
            }
        }
        __syncthreads();

        float sacc[8][4];
#pragma unroll
        for (int nt = 0; nt < 8; nt++)
#pragma unroll
            for (int i = 0; i < 4; i++) sacc[nt][i] = 0.f;

#pragma unroll
        for (int kk = 0; kk < 4; kk++) {
            int c = kk * 16;
            unsigned af[4], bf[4][4];
            ldsm_x4(af, shQ + (unsigned)(a_off + c) * 2);
#pragma unroll
            for (int p = 0; p < 4; p++)
                ldsm_x4(bf[p], shK + (unsigned)(b_off + p * 16 * AST + c) * 2);
#pragma unroll
            for (int nt = 0; nt < 8; nt++)
                mma_f16(sacc[nt], af, &bf[nt >> 1][(nt & 1) * 2]);
        }

        float rmax0 = -1e30f, rmax1 = -1e30f;
#pragma unroll
        for (int nt = 0; nt < 8; nt++) {
#pragma unroll
            for (int e = 0; e < 2; e++) {
                int j = cs + nt * 8 + 2 * t + e;
                if (!((j <= iq0) && (j > iq0 - WIN))) sacc[nt][e] = -1e30f;
                if (!((j <= iq1) && (j > iq1 - WIN))) sacc[nt][2 + e] = -1e30f;
                rmax0 = fmaxf(rmax0, sacc[nt][e]);
                rmax1 = fmaxf(rmax1, sacc[nt][2 + e]);
            }
        }
#pragma unroll
        for (int msk = 1; msk < 4; msk <<= 1) {
            rmax0 = fmaxf(rmax0, __shfl_xor_sync(0xffffffffu, rmax0, msk));
            rmax1 = fmaxf(rmax1, __shfl_xor_sync(0xffffffffu, rmax1, msk));
        }

        float mn0 = fmaxf(m0, rmax0);
        float mn1 = fmaxf(m1, rmax1);
        float cor0 = __expf(m0 - mn0);
        float cor1 = __expf(m1 - mn1);
        m0 = mn0; m1 = mn1;

        float rs0 = 0.f, rs1 = 0.f;
#pragma unroll
        for (int nt = 0; nt < 8; nt++) {
            float p0 = __expf(sacc[nt][0] - mn0);
            float p1 = __expf(sacc[nt][1] - mn0);
            float p2 = __expf(sacc[nt][2] - mn1);
            float p3 = __expf(sacc[nt][3] - mn1);
            rs0 += p0 + p1;
            rs1 += p2 + p3;
            int col = nt * 8 + 2 * t;
            *(__half2*)(Ps + (rbase + g) * AST + col)     = __floats2half2_rn(p0, p1);
            *(__half2*)(Ps + (rbase + g + 8) * AST + col) = __floats2half2_rn(p2, p3);
        }
#pragma unroll
        for (int msk = 1; msk < 4; msk <<= 1) {
            rs0 += __shfl_xor_sync(0xffffffffu, rs0, msk);
            rs1 += __shfl_xor_sync(0xffffffffu, rs1, msk);
        }
        l0 = l0 * cor0 + rs0;
        l1 = l1 * cor1 + rs1;
#pragma unroll
        for (int nt = 0; nt < 8; nt++) {
            oacc[nt][0] *= cor0; oacc[nt][1] *= cor0;
            oacc[nt][2] *= cor1; oacc[nt][3] *= cor1;
        }
        __syncwarp();

#pragma unroll
        for (int kk = 0; kk < 4; kk++) {
            int c = kk * 16;
            unsigned af[4], bf[4][4];
            ldsm_x4(af, shP + (unsigned)(a_off + c) * 2);
#pragma unroll
            for (int p = 0; p < 4; p++)
                ldsm_x4(bf[p], shV + (unsigned)(b_off + p * 16 * AST + c) * 2);
#pragma unroll
            for (int nt = 0; nt < 8; nt++)
                mma_f16(oacc[nt], af, &bf[nt >> 1][(nt & 1) * 2]);
        }
    }

    float inv0 = 1.f / l0;
    float inv1 = 1.f / l1;
    int b = bh / NHEADS;
    int h = bh % NHEADS;
    __half* O0 = g_O + (size_t)(b * SEQ + iq0) * D_MODEL + h * HD;
    __half* O1 = g_O + (size_t)(b * SEQ + iq1) * D_MODEL + h * HD;
#pragma unroll
    for (int nt = 0; nt < 8; nt++) {
        int d = nt * 8 + 2 * t;
        *(__half2*)(O0 + d) = __floats2half2_rn(oacc[nt][0] * inv0, oacc[nt][1] * inv0);
        *(__half2*)(O1 + d) = __floats2half2_rn(oacc[nt][2] * inv1, oacc[nt][3] * inv1);
    }
}

// ---------------------------------------------------------------------------
extern "C" void kernel_launch(void* const* d_in, const int* in_sizes, int n_in,
                              void* d_out, int out_size)
{
    const float* x  = (const float*)d_in[0];
    const float* w1 = (const float*)d_in[1];
    const float* b1 = (const float*)d_in[2];
    const float* w2 = (const float*)d_in[3];
    const float* b2 = (const float*)d_in[4];
    float* out = (float*)d_out;

    const int M = BATCH * SEQ;

    __half *cx, *cw1, *cw2;
    cudaGetSymbolAddress((void**)&cx,  c_x);
    cudaGetSymbolAddress((void**)&cw1, c_w1);
    cudaGetSymbolAddress((void**)&cw2, c_w2);

    // 0) fp32 -> fp16 conversions
    {
        int n4x = M * D_MODEL / 4;
        cvt_f16<<<(n4x + 255) / 256, 256>>>((const float4*)x, (uint2*)cx, n4x);
        int n4w1 = 3 * D_MODEL * D_MODEL / 4;
        cvt_f16<<<(n4w1 + 255) / 256, 256>>>((const float4*)w1, (uint2*)cw1, n4w1);
        int n4w2 = D_MODEL * D_MODEL / 4;
        cvt_f16<<<(n4w2 + 255) / 256, 256>>>((const float4*)w2, (uint2*)cw2, n4w2);
    }

    const int gemm_smem = 2 * NSTG * STG_BYTES;   // 110592 B

    // 1) QKV projection (fp16 mma, 512 threads, occ 50%)
    {
        cudaFuncSetAttribute(gemm_f16<0>,
                             cudaFuncAttributeMaxDynamicSharedMemorySize, gemm_smem);
        dim3 grid(3 * D_MODEL / 128, M / 128);
        gemm_f16<0><<<grid, 512, gemm_smem>>>(cx, cw1, b1, nullptr, M, 3 * D_MODEL, D_MODEL);
    }

    // 2) Sliding-window attention (fp16 mma, Q-tile 64)
    {
        int smem = 4 * 64 * AST * sizeof(__half);  // 36864 B
        cudaFuncSetAttribute(attn_mma,
                             cudaFuncAttributeMaxDynamicSharedMemorySize, smem);
        dim3 grid(SEQ / 64, BATCH * NHEADS);
        attn_mma<<<grid, 128, smem>>>();
    }

    // 3) Output projection (fp16 mma, 512 threads)
    {
        cudaFuncSetAttribute(gemm_f16<1>,
                             cudaFuncAttributeMaxDynamicSharedMemorySize, gemm_smem);
        dim3 grid(D_MODEL / 128, M / 128);
        gemm_f16<1><<<grid, 512, gemm_smem>>>(nullptr, cw2, b2, out, M, D_MODEL, D_MODEL);
    }
}

// round 12
// speedup vs baseline: 1.0497x; 1.0497x over previous
#include <cuda_runtime.h>
#include <cuda_fp16.h>
#include <math.h>
#include <stdint.h>

#define D_MODEL 1024
#define NHEADS  16
#define HD      64
#define SEQ     2048
#define BATCH   2
#define WIN     256

// Scratch (allocation-free: __device__ globals). All fp16.
__device__ __half g_Q[BATCH * NHEADS * SEQ * HD];   // [b][h][l][d]
__device__ __half g_K[BATCH * NHEADS * SEQ * HD];
__device__ __half g_V[BATCH * NHEADS * SEQ * HD];
__device__ __half g_O[BATCH * SEQ * D_MODEL];       // [b][l][h*64+d]
__device__ __half c_x [BATCH * SEQ * D_MODEL];
__device__ __half c_w1[3 * D_MODEL * D_MODEL];
__device__ __half c_w2[D_MODEL * D_MODEL];

__device__ __forceinline__ void mma_f16(float c[4], const unsigned a[4], const unsigned b[2]) {
    asm volatile(
        "mma.sync.aligned.m16n8k16.row.col.f32.f16.f16.f32 "
        "{%0,%1,%2,%3}, {%4,%5,%6,%7}, {%8,%9}, {%0,%1,%2,%3};\n"
        : "+f"(c[0]), "+f"(c[1]), "+f"(c[2]), "+f"(c[3])
        : "r"(a[0]), "r"(a[1]), "r"(a[2]), "r"(a[3]),
          "r"(b[0]), "r"(b[1]));
}

__device__ __forceinline__ void ldsm_x4(unsigned a[4], unsigned saddr) {
    asm volatile("ldmatrix.sync.aligned.m8n8.x4.shared.b16 {%0,%1,%2,%3}, [%4];"
        : "=r"(a[0]), "=r"(a[1]), "=r"(a[2]), "=r"(a[3]) : "r"(saddr));
}

__device__ __forceinline__ void ldsm_x4_trans(unsigned a[4], unsigned saddr) {
    asm volatile("ldmatrix.sync.aligned.m8n8.x4.trans.shared.b16 {%0,%1,%2,%3}, [%4];"
        : "=r"(a[0]), "=r"(a[1]), "=r"(a[2]), "=r"(a[3]) : "r"(saddr));
}

// ---------------------------------------------------------------------------
// fp32 -> fp16 bulk converter
// ---------------------------------------------------------------------------
__global__ void cvt_f16(const float4* __restrict__ in, uint2* __restrict__ out, int n4)
{
    int i = blockIdx.x * blockDim.x + threadIdx.x;
    if (i < n4) {
        float4 v = in[i];
        __half2 h01 = __floats2half2_rn(v.x, v.y);
        __half2 h23 = __floats2half2_rn(v.z, v.w);
        uint2 u;
        u.x = *(unsigned*)&h01;
        u.y = *(unsigned*)&h23;
        out[i] = u;
    }
}

// ---------------------------------------------------------------------------
// FP16 NT GEMM (fp32 accum), BK=64, 3-stage cp.async pipeline + ldmatrix.
// R9 configuration (best known): 256 threads (2x4 warps), warp tile 64x32.
// ---------------------------------------------------------------------------
#define SSTR 72
#define BK   64
#define STG_HALVES (128 * SSTR)
#define STG_BYTES  (STG_HALVES * 2)
#define NSTG 3

template <int MODE>
__global__ __launch_bounds__(256, 2)
void gemm_f16(const __half* __restrict__ A, const __half* __restrict__ W,
              const float* __restrict__ bias, float* __restrict__ Cout,
              int M, int N, int K)
{
    extern __shared__ __half sh[];
    __half* AsBase = sh;
    __half* BsBase = sh + NSTG * STG_HALVES;

    const __half* Ap = (MODE == 1) ? (const __half*)g_O : A;

    int tid  = threadIdx.x;
    int lane = tid & 31;
    int wid  = tid >> 5;
    int wm = (wid >> 2) * 64;
    int wn = (wid & 3) * 32;
    int bm = blockIdx.y * 128;
    int bn = blockIdx.x * 128;
    int g = lane >> 2;
    int t = lane & 3;
    int lr = lane & 7;

    int a_off = (wm + lr + (((lane >> 3) & 1) ? 8 : 0)) * SSTR + ((lane >> 4) ? 8 : 0);
    int b_off = (wn + lr + ((lane >> 4) ? 8 : 0)) * SSTR + (((lane >> 3) & 1) ? 8 : 0);

    unsigned shA = (unsigned)__cvta_generic_to_shared(AsBase);
    unsigned shB = (unsigned)__cvta_generic_to_shared(BsBase);

    float acc[4][4][4];
#pragma unroll
    for (int mt = 0; mt < 4; mt++)
#pragma unroll
        for (int nt = 0; nt < 4; nt++)
#pragma unroll
            for (int i = 0; i < 4; i++) acc[mt][nt][i] = 0.f;

    auto issue = [&](int s, int k0) {
        __half* dA = AsBase + s * STG_HALVES;
        __half* dB = BsBase + s * STG_HALVES;
#pragma unroll
        for (int r = 0; r < 4; r++) {
            int id  = tid + r * 256;
            int row = id >> 3;
            int c   = id & 7;
            const __half* ga = Ap + (size_t)(bm + row) * K + k0 + c * 8;
            const __half* gb = W  + (size_t)(bn + row) * K + k0 + c * 8;
            unsigned sa = (unsigned)__cvta_generic_to_shared(dA + row * SSTR + c * 8);
            unsigned sb = (unsigned)__cvta_generic_to_shared(dB + row * SSTR + c * 8);
            asm volatile("cp.async.cg.shared.global [%0], [%1], 16;\n" :: "r"(sa), "l"(ga));
            asm volatile("cp.async.cg.shared.global [%0], [%1], 16;\n" :: "r"(sb), "l"(gb));
        }
        asm volatile("cp.async.commit_group;\n");
    };

    const int TILES = K / BK;
    issue(0, 0);
    issue(1, BK);

    int stage = 0, fill = 2;

    for (int t2 = 0; t2 < TILES; t2++) {
        asm volatile("cp.async.wait_group 1;\n" ::: "memory");
        __syncthreads();

        if (t2 + 2 < TILES) issue(fill, (t2 + 2) * BK);

        unsigned stA = shA + stage * STG_BYTES;
        unsigned stB = shB + stage * STG_BYTES;

#pragma unroll
        for (int ks = 0; ks < 4; ks++) {
            int kk = ks * 16;
            unsigned af[4][4], bf[2][4];
#pragma unroll
            for (int mt = 0; mt < 4; mt++)
                ldsm_x4(af[mt], stA + (unsigned)(a_off + mt * 16 * SSTR + kk) * 2);
#pragma unroll
            for (int p = 0; p < 2; p++)
                ldsm_x4(bf[p], stB + (unsigned)(b_off + p * 16 * SSTR + kk) * 2);
#pragma unroll
            for (int mt = 0; mt < 4; mt++)
#pragma unroll
                for (int nt = 0; nt < 4; nt++)
                    mma_f16(acc[mt][nt], af[mt], &bf[nt >> 1][(nt & 1) * 2]);
        }

        fill  = stage;
        stage = (stage == 2) ? 0 : stage + 1;
    }

#pragma unroll
    for (int mt = 0; mt < 4; mt++) {
#pragma unroll
        for (int nt = 0; nt < 4; nt++) {
#pragma unroll
            for (int i = 0; i < 4; i++) {
                int m = bm + wm + mt * 16 + g + ((i >> 1) ? 8 : 0);
                int n = bn + wn + nt * 8 + t * 2 + (i & 1);
                float v = acc[mt][nt][i] + bias[n];
                if (MODE == 0) {
                    int part   = n >> 10;
                    int within = n & 1023;
                    int h = within >> 6;
                    int d = within & 63;
                    int b = m >> 11;
                    int l = m & 2047;
                    size_t dst = ((size_t)(b * NHEADS + h) * SEQ + l) * HD + d;
                    __half* base = (part == 0) ? g_Q : (part == 1) ? g_K : g_V;
                    base[dst] = __float2half_rn(v);
                } else {
                    Cout[(size_t)m * N + n] = v;
                }
            }
        }
    }
}

// ---------------------------------------------------------------------------
// Sliding-window attention, fp16 mma + ldmatrix.
// Q-tile 64, 128 threads (4 warps x 16 query rows).
// V stays in natural [j][d] layout; P*V B-fragments via ldmatrix.x4.trans
// (FlashAttention-2 style) -> no scalar transpose staging.
// ---------------------------------------------------------------------------
#define AST 72

__global__ __launch_bounds__(128)
void attn_mma()
{
    extern __shared__ __half smh[];
    __half* Qs = smh;                 // [q][d]  64 x AST
    __half* Ks = smh + 64 * AST;      // [j][d]
    __half* Vs = smh + 2 * 64 * AST;  // [j][d]  (natural layout)
    __half* Ps = smh + 3 * 64 * AST;  // [q][j]

    int tid  = threadIdx.x;
    int lane = tid & 31;
    int wid  = tid >> 5;
    int g = lane >> 2;
    int t = lane & 3;
    int lr = lane & 7;

    int bh = blockIdx.y;
    int i0 = blockIdx.x * 64;

    const __half* Qg = g_Q + (size_t)bh * SEQ * HD;
    const __half* Kg = g_K + (size_t)bh * SEQ * HD;
    const __half* Vg = g_V + (size_t)bh * SEQ * HD;

    int rbase = wid * 16;
    int a_off = (rbase + lr + (((lane >> 3) & 1) ? 8 : 0)) * AST + ((lane >> 4) ? 8 : 0);
    int b_off = (lr + ((lane >> 4) ? 8 : 0)) * AST + (((lane >> 3) & 1) ? 8 : 0);
    // V trans-fragment offset: lanes address k-rows (j), n offset = d
    // rows: lr + 8*bit3 (k within 16-window); cols: 8*bit4 (n within 16-group)
    int vb_off = (lr + (((lane >> 3) & 1) ? 8 : 0)) * AST + ((lane >> 4) ? 8 : 0);

    unsigned shQ = (unsigned)__cvta_generic_to_shared(Qs);
    unsigned shK = (unsigned)__cvta_generic_to_shared(Ks);
    unsigned shV = (unsigned)__cvta_generic_to_shared(Vs);
    unsigned shP = (unsigned)__cvta_generic_to_shared(Ps);

    // Load Q tile, scale by 0.125 (exact exponent shift)
    {
        int q = tid >> 1, half_sel = tid & 1;
        const __half2 s2 = __floats2half2_rn(0.125f, 0.125f);
#pragma unroll
        for (int v = 0; v < 4; v++) {
            int c8 = half_sel * 32 + v * 8;
            uint2 raw = *(const uint2*)(Qg + (size_t)(i0 + q) * HD + c8);
            __half2 h0 = __hmul2(*(__half2*)&raw.x, s2);
            __half2 h1 = __hmul2(*(__half2*)&raw.y, s2);
            uint2 raw2 = *(const uint2*)(Qg + (size_t)(i0 + q) * HD + c8 + 4);
            __half2 h2 = __hmul2(*(__half2*)&raw2.x, s2);
            __half2 h3 = __hmul2(*(__half2*)&raw2.y, s2);
            __half* dst = Qs + q * AST + c8;
            *(__half2*)(dst)     = h0;
            *(__half2*)(dst + 2) = h1;
            *(__half2*)(dst + 4) = h2;
            *(__half2*)(dst + 6) = h3;
        }
    }

    int iq0 = i0 + rbase + g;
    int iq1 = iq0 + 8;

    float m0 = -1e30f, m1 = -1e30f, l0 = 0.f, l1 = 0.f;
    float oacc[8][4];
#pragma unroll
    for (int nt = 0; nt < 8; nt++)
#pragma unroll
        for (int i = 0; i < 4; i++) oacc[nt][i] = 0.f;

    int kv_lo = i0 - (WIN - 1);
    if (kv_lo < 0) kv_lo = 0;
    int cs0 = (kv_lo / 64) * 64;

    for (int cs = cs0; cs <= i0; cs += 64) {
        __syncthreads();
        // Stage K and V, both natural [j][d] — pure uint4 copies
        {
            int j = tid >> 1, half_sel = tid & 1;
            int c16 = half_sel * 32;
#pragma unroll
            for (int v = 0; v < 2; v++) {
                int c = c16 + v * 16;
                *(uint4*)(Ks + j * AST + c) =
                    *(const uint4*)(Kg + (size_t)(cs + j) * HD + c);
                *(uint4*)(Ks + j * AST + c + 8) =
                    *(const uint4*)(Kg + (size_t)(cs + j) * HD + c + 8);
                *(uint4*)(Vs + j * AST + c) =
                    *(const uint4*)(Vg + (size_t)(cs + j) * HD + c);
                *(uint4*)(Vs + j * AST + c + 8) =
                    *(const uint4*)(Vg + (size_t)(cs + j) * HD + c + 8);
            }
        }
        __syncthreads();

        // S = Q*K^T
        float sacc[8][4];
#pragma unroll
        for (int nt = 0; nt < 8; nt++)
#pragma unroll
            for (int i = 0; i < 4; i++) sacc[nt][i] = 0.f;

#pragma unroll
        for (int kk = 0; kk < 4; kk++) {
            int c = kk * 16;
            unsigned af[4], bf[4][4];
            ldsm_x4(af, shQ + (unsigned)(a_off + c) * 2);
#pragma unroll
            for (int p = 0; p < 4; p++)
                ldsm_x4(bf[p], shK + (unsigned)(b_off + p * 16 * AST + c) * 2);
#pragma unroll
            for (int nt = 0; nt < 8; nt++)
                mma_f16(sacc[nt], af, &bf[nt >> 1][(nt & 1) * 2]);
        }

        // Mask + online softmax
        float rmax0 = -1e30f, rmax1 = -1e30f;
#pragma unroll
        for (int nt = 0; nt < 8; nt++) {
#pragma unroll
            for (int e = 0; e < 2; e++) {
                int j = cs + nt * 8 + 2 * t + e;
                if (!((j <= iq0) && (j > iq0 - WIN))) sacc[nt][e] = -1e30f;
                if (!((j <= iq1) && (j > iq1 - WIN))) sacc[nt][2 + e] = -1e30f;
                rmax0 = fmaxf(rmax0, sacc[nt][e]);
                rmax1 = fmaxf(rmax1, sacc[nt][2 + e]);
            }
        }
#pragma unroll
        for (int msk = 1; msk < 4; msk <<= 1) {
            rmax0 = fmaxf(rmax0, __shfl_xor_sync(0xffffffffu, rmax0, msk));
            rmax1 = fmaxf(rmax1, __shfl_xor_sync(0xffffffffu, rmax1, msk));
        }

        float mn0 = fmaxf(m0, rmax0);
        float mn1 = fmaxf(m1, rmax1);
        float cor0 = __expf(m0 - mn0);
        float cor1 = __expf(m1 - mn1);
        m0 = mn0; m1 = mn1;

        float rs0 = 0.f, rs1 = 0.f;
#pragma unroll
        for (int nt = 0; nt < 8; nt++) {
            float p0 = __expf(sacc[nt][0] - mn0);
            float p1 = __expf(sacc[nt][1] - mn0);
            float p2 = __expf(sacc[nt][2] - mn1);
            float p3 = __expf(sacc[nt][3] - mn1);
            rs0 += p0 + p1;
            rs1 += p2 + p3;
            int col = nt * 8 + 2 * t;
            *(__half2*)(Ps + (rbase + g) * AST + col)     = __floats2half2_rn(p0, p1);
            *(__half2*)(Ps + (rbase + g + 8) * AST + col) = __floats2half2_rn(p2, p3);
        }
#pragma unroll
        for (int msk = 1; msk < 4; msk <<= 1) {
            rs0 += __shfl_xor_sync(0xffffffffu, rs0, msk);
            rs1 += __shfl_xor_sync(0xffffffffu, rs1, msk);
        }
        l0 = l0 * cor0 + rs0;
        l1 = l1 * cor1 + rs1;
#pragma unroll
        for (int nt = 0; nt < 8; nt++) {
            oacc[nt][0] *= cor0; oacc[nt][1] *= cor0;
            oacc[nt][2] *= cor1; oacc[nt][3] *= cor1;
        }
        __syncwarp();

        // O += P * V   (B fragments from natural-layout V via ldmatrix.trans)
#pragma unroll
        for (int kk = 0; kk < 4; kk++) {
            int c = kk * 16;                  // k (=j) window base
            unsigned af[4], bf[4][4];
            ldsm_x4(af, shP + (unsigned)(a_off + c) * 2);
#pragma unroll
            for (int p = 0; p < 4; p++)       // n (=d) group of 16
                ldsm_x4_trans(bf[p], shV + (unsigned)(vb_off + c * AST + p * 16) * 2);
#pragma unroll
            for (int nt = 0; nt < 8; nt++)
                mma_f16(oacc[nt], af, &bf[nt >> 1][(nt & 1) * 2]);
        }
    }

    // Normalize + write fp16 O
    float inv0 = 1.f / l0;
    float inv1 = 1.f / l1;
    int b = bh / NHEADS;
    int h = bh % NHEADS;
    __half* O0 = g_O + (size_t)(b * SEQ + iq0) * D_MODEL + h * HD;
    __half* O1 = g_O + (size_t)(b * SEQ + iq1) * D_MODEL + h * HD;
#pragma unroll
    for (int nt = 0; nt < 8; nt++) {
        int d = nt * 8 + 2 * t;
        *(__half2*)(O0 + d) = __floats2half2_rn(oacc[nt][0] * inv0, oacc[nt][1] * inv0);
        *(__half2*)(O1 + d) = __floats2half2_rn(oacc[nt][2] * inv1, oacc[nt][3] * inv1);
    }
}

// ---------------------------------------------------------------------------
extern "C" void kernel_launch(void* const* d_in, const int* in_sizes, int n_in,
                              void* d_out, int out_size)
{
    const float* x  = (const float*)d_in[0];
    const float* w1 = (const float*)d_in[1];
    const float* b1 = (const float*)d_in[2];
    const float* w2 = (const float*)d_in[3];
    const float* b2 = (const float*)d_in[4];
    float* out = (float*)d_out;

    const int M = BATCH * SEQ;

    __half *cx, *cw1, *cw2;
    cudaGetSymbolAddress((void**)&cx,  c_x);
    cudaGetSymbolAddress((void**)&cw1, c_w1);
    cudaGetSymbolAddress((void**)&cw2, c_w2);

    // 0) fp32 -> fp16 conversions
    {
        int n4x = M * D_MODEL / 4;
        cvt_f16<<<(n4x + 255) / 256, 256>>>((const float4*)x, (uint2*)cx, n4x);
        int n4w1 = 3 * D_MODEL * D_MODEL / 4;
        cvt_f16<<<(n4w1 + 255) / 256, 256>>>((const float4*)w1, (uint2*)cw1, n4w1);
        int n4w2 = D_MODEL * D_MODEL / 4;
        cvt_f16<<<(n4w2 + 255) / 256, 256>>>((const float4*)w2, (uint2*)cw2, n4w2);
    }

    const int gemm_smem = 2 * NSTG * STG_BYTES;   // 110592 B

    // 1) QKV projection (fp16 mma, R9 config)
    {
        cudaFuncSetAttribute(gemm_f16<0>,
                             cudaFuncAttributeMaxDynamicSharedMemorySize, gemm_smem);
        dim3 grid(3 * D_MODEL / 128, M / 128);
        gemm_f16<0><<<grid, 256, gemm_smem>>>(cx, cw1, b1, nullptr, M, 3 * D_MODEL, D_MODEL);
    }

    // 2) Sliding-window attention (fp16 mma, Q-tile 64, trans-V)
    {
        int smem = 4 * 64 * AST * sizeof(__half);  // 36864 B
        cudaFuncSetAttribute(attn_mma,
                             cudaFuncAttributeMaxDynamicSharedMemorySize, smem);
        dim3 grid(SEQ / 64, BATCH * NHEADS);
        attn_mma<<<grid, 128, smem>>>();
    }

    // 3) Output projection (fp16 mma, R9 config)
    {
        cudaFuncSetAttribute(gemm_f16<1>,
                             cudaFuncAttributeMaxDynamicSharedMemorySize, gemm_smem);
        dim3 grid(D_MODEL / 128, M / 128);
        gemm_f16<1><<<grid, 256, gemm_smem>>>(nullptr, cw2, b2, out, M, D_MODEL, D_MODEL);
    }
}

// round 13
// speedup vs baseline: 1.1254x; 1.0722x over previous
#include <cuda_runtime.h>
#include <cuda_fp16.h>
#include <math.h>
#include <stdint.h>

#define D_MODEL 1024
#define NHEADS  16
#define HD      64
#define SEQ     2048
#define BATCH   2
#define WIN     256

// Scratch (allocation-free: __device__ globals). All fp16.
__device__ __half g_Q[BATCH * NHEADS * SEQ * HD];   // [b][h][l][d]
__device__ __half g_K[BATCH * NHEADS * SEQ * HD];
__device__ __half g_V[BATCH * NHEADS * SEQ * HD];
__device__ __half g_O[BATCH * SEQ * D_MODEL];       // [b][l][h*64+d]
__device__ __half c_x [BATCH * SEQ * D_MODEL];
__device__ __half c_w1[3 * D_MODEL * D_MODEL];
__device__ __half c_w2[D_MODEL * D_MODEL];

__device__ __forceinline__ void mma_f16(float c[4], const unsigned a[4], const unsigned b[2]) {
    asm volatile(
        "mma.sync.aligned.m16n8k16.row.col.f32.f16.f16.f32 "
        "{%0,%1,%2,%3}, {%4,%5,%6,%7}, {%8,%9}, {%0,%1,%2,%3};\n"
        : "+f"(c[0]), "+f"(c[1]), "+f"(c[2]), "+f"(c[3])
        : "r"(a[0]), "r"(a[1]), "r"(a[2]), "r"(a[3]),
          "r"(b[0]), "r"(b[1]));
}

__device__ __forceinline__ void ldsm_x4(unsigned a[4], unsigned saddr) {
    asm volatile("ldmatrix.sync.aligned.m8n8.x4.shared.b16 {%0,%1,%2,%3}, [%4];"
        : "=r"(a[0]), "=r"(a[1]), "=r"(a[2]), "=r"(a[3]) : "r"(saddr));
}

__device__ __forceinline__ void ldsm_x4_trans(unsigned a[4], unsigned saddr) {
    asm volatile("ldmatrix.sync.aligned.m8n8.x4.trans.shared.b16 {%0,%1,%2,%3}, [%4];"
        : "=r"(a[0]), "=r"(a[1]), "=r"(a[2]), "=r"(a[3]) : "r"(saddr));
}

// ---------------------------------------------------------------------------
// Fused fp32 -> fp16 bulk converter for x, w1, w2 (one launch)
// ---------------------------------------------------------------------------
__global__ void cvt_all(const float4* __restrict__ x,  uint2* __restrict__ cx,  int n4x,
                        const float4* __restrict__ w1, uint2* __restrict__ cw1, int n4w1,
                        const float4* __restrict__ w2, uint2* __restrict__ cw2, int n4w2)
{
    int i = blockIdx.x * blockDim.x + threadIdx.x;
    const float4* src;
    uint2* dst;
    int idx;
    if (i < n4x)                   { src = x;  dst = cx;  idx = i; }
    else if (i < n4x + n4w1)       { src = w1; dst = cw1; idx = i - n4x; }
    else if (i < n4x + n4w1 + n4w2){ src = w2; dst = cw2; idx = i - n4x - n4w1; }
    else return;
    float4 v = src[idx];
    __half2 h01 = __floats2half2_rn(v.x, v.y);
    __half2 h23 = __floats2half2_rn(v.z, v.w);
    uint2 u;
    u.x = *(unsigned*)&h01;
    u.y = *(unsigned*)&h23;
    dst[idx] = u;
}

// ---------------------------------------------------------------------------
// FP16 NT GEMM (fp32 accum), BK=64, 3-stage cp.async pipeline + ldmatrix.
// R9 configuration (at legacy-HMMA ceiling): 256 threads, warp tile 64x32.
// ---------------------------------------------------------------------------
#define SSTR 72
#define BK   64
#define STG_HALVES (128 * SSTR)
#define STG_BYTES  (STG_HALVES * 2)
#define NSTG 3

template <int MODE>
__global__ __launch_bounds__(256, 2)
void gemm_f16(const __half* __restrict__ A, const __half* __restrict__ W,
              const float* __restrict__ bias, float* __restrict__ Cout,
              int M, int N, int K)
{
    extern __shared__ __half sh[];
    __half* AsBase = sh;
    __half* BsBase = sh + NSTG * STG_HALVES;

    const __half* Ap = (MODE == 1) ? (const __half*)g_O : A;

    int tid  = threadIdx.x;
    int lane = tid & 31;
    int wid  = tid >> 5;
    int wm = (wid >> 2) * 64;
    int wn = (wid & 3) * 32;
    int bm = blockIdx.y * 128;
    int bn = blockIdx.x * 128;
    int g = lane >> 2;
    int t = lane & 3;
    int lr = lane & 7;

    int a_off = (wm + lr + (((lane >> 3) & 1) ? 8 : 0)) * SSTR + ((lane >> 4) ? 8 : 0);
    int b_off = (wn + lr + ((lane >> 4) ? 8 : 0)) * SSTR + (((lane >> 3) & 1) ? 8 : 0);

    unsigned shA = (unsigned)__cvta_generic_to_shared(AsBase);
    unsigned shB = (unsigned)__cvta_generic_to_shared(BsBase);

    float acc[4][4][4];
#pragma unroll
    for (int mt = 0; mt < 4; mt++)
#pragma unroll
        for (int nt = 0; nt < 4; nt++)
#pragma unroll
            for (int i = 0; i < 4; i++) acc[mt][nt][i] = 0.f;

    auto issue = [&](int s, int k0) {
        __half* dA = AsBase + s * STG_HALVES;
        __half* dB = BsBase + s * STG_HALVES;
#pragma unroll
        for (int r = 0; r < 4; r++) {
            int id  = tid + r * 256;
            int row = id >> 3;
            int c   = id & 7;
            const __half* ga = Ap + (size_t)(bm + row) * K + k0 + c * 8;
            const __half* gb = W  + (size_t)(bn + row) * K + k0 + c * 8;
            unsigned sa = (unsigned)__cvta_generic_to_shared(dA + row * SSTR + c * 8);
            unsigned sb = (unsigned)__cvta_generic_to_shared(dB + row * SSTR + c * 8);
            asm volatile("cp.async.cg.shared.global [%0], [%1], 16;\n" :: "r"(sa), "l"(ga));
            asm volatile("cp.async.cg.shared.global [%0], [%1], 16;\n" :: "r"(sb), "l"(gb));
        }
        asm volatile("cp.async.commit_group;\n");
    };

    const int TILES = K / BK;
    issue(0, 0);
    issue(1, BK);

    int stage = 0, fill = 2;

    for (int t2 = 0; t2 < TILES; t2++) {
        asm volatile("cp.async.wait_group 1;\n" ::: "memory");
        __syncthreads();

        if (t2 + 2 < TILES) issue(fill, (t2 + 2) * BK);

        unsigned stA = shA + stage * STG_BYTES;
        unsigned stB = shB + stage * STG_BYTES;

#pragma unroll
        for (int ks = 0; ks < 4; ks++) {
            int kk = ks * 16;
            unsigned af[4][4], bf[2][4];
#pragma unroll
            for (int mt = 0; mt < 4; mt++)
                ldsm_x4(af[mt], stA + (unsigned)(a_off + mt * 16 * SSTR + kk) * 2);
#pragma unroll
            for (int p = 0; p < 2; p++)
                ldsm_x4(bf[p], stB + (unsigned)(b_off + p * 16 * SSTR + kk) * 2);
#pragma unroll
            for (int mt = 0; mt < 4; mt++)
#pragma unroll
                for (int nt = 0; nt < 4; nt++)
                    mma_f16(acc[mt][nt], af[mt], &bf[nt >> 1][(nt & 1) * 2]);
        }

        fill  = stage;
        stage = (stage == 2) ? 0 : stage + 1;
    }

#pragma unroll
    for (int mt = 0; mt < 4; mt++) {
#pragma unroll
        for (int nt = 0; nt < 4; nt++) {
#pragma unroll
            for (int i = 0; i < 4; i++) {
                int m = bm + wm + mt * 16 + g + ((i >> 1) ? 8 : 0);
                int n = bn + wn + nt * 8 + t * 2 + (i & 1);
                float v = acc[mt][nt][i] + bias[n];
                if (MODE == 0) {
                    int part   = n >> 10;
                    int within = n & 1023;
                    int h = within >> 6;
                    int d = within & 63;
                    int b = m >> 11;
                    int l = m & 2047;
                    size_t dst = ((size_t)(b * NHEADS + h) * SEQ + l) * HD + d;
                    __half* base = (part == 0) ? g_Q : (part == 1) ? g_K : g_V;
                    base[dst] = __float2half_rn(v);
                } else {
                    Cout[(size_t)m * N + n] = v;
                }
            }
        }
    }
}

// ---------------------------------------------------------------------------
// Sliding-window attention, fp16 mma + ldmatrix + 3-stage cp.async K/V pipeline.
// Q-tile 64, 128 threads (4 warps x 16 query rows). V natural layout + ldsm.trans.
// Smem: Q | 3 stages of (K,V) | P  = 74 KB.
// ---------------------------------------------------------------------------
#define AST 72
#define ATT_STG_HALVES (2 * 64 * AST)          // K + V per stage
#define ATT_STG_BYTES  (ATT_STG_HALVES * 2)    // 18432

__global__ __launch_bounds__(128)
void attn_mma()
{
    extern __shared__ __half smh[];
    __half* Qs     = smh;                         // [q][d]  64 x AST
    __half* KVbase = smh + 64 * AST;              // 3 stages of K[64xAST] + V[64xAST]
    __half* Ps     = KVbase + 3 * ATT_STG_HALVES; // [q][j]  64 x AST

    int tid  = threadIdx.x;
    int lane = tid & 31;
    int wid  = tid >> 5;
    int g = lane >> 2;
    int t = lane & 3;
    int lr = lane & 7;

    int bh = blockIdx.y;
    int i0 = blockIdx.x * 64;

    const __half* Qg = g_Q + (size_t)bh * SEQ * HD;
    const __half* Kg = g_K + (size_t)bh * SEQ * HD;
    const __half* Vg = g_V + (size_t)bh * SEQ * HD;

    int rbase = wid * 16;
    int a_off = (rbase + lr + (((lane >> 3) & 1) ? 8 : 0)) * AST + ((lane >> 4) ? 8 : 0);
    int b_off = (lr + ((lane >> 4) ? 8 : 0)) * AST + (((lane >> 3) & 1) ? 8 : 0);
    int vb_off = (lr + (((lane >> 3) & 1) ? 8 : 0)) * AST + ((lane >> 4) ? 8 : 0);

    unsigned shQ  = (unsigned)__cvta_generic_to_shared(Qs);
    unsigned shKV = (unsigned)__cvta_generic_to_shared(KVbase);
    unsigned shP  = (unsigned)__cvta_generic_to_shared(Ps);

    int kv_lo = i0 - (WIN - 1);
    if (kv_lo < 0) kv_lo = 0;
    int cs0 = (kv_lo / 64) * 64;
    int n_chunks = (i0 - cs0) / 64 + 1;

    // cp.async stage fill: K and V chunk (each 64 rows x 128B = 512 x 16B; 4 per thread)
    auto issueKV = [&](int s, int cs) {
        __half* dK = KVbase + s * ATT_STG_HALVES;
        __half* dV = dK + 64 * AST;
#pragma unroll
        for (int r = 0; r < 4; r++) {
            int id  = tid + r * 128;
            int row = id >> 3;
            int c   = id & 7;
            const __half* gk = Kg + (size_t)(cs + row) * HD + c * 8;
            const __half* gv = Vg + (size_t)(cs + row) * HD + c * 8;
            unsigned sk = (unsigned)__cvta_generic_to_shared(dK + row * AST + c * 8);
            unsigned sv = (unsigned)__cvta_generic_to_shared(dV + row * AST + c * 8);
            asm volatile("cp.async.cg.shared.global [%0], [%1], 16;\n" :: "r"(sk), "l"(gk));
            asm volatile("cp.async.cg.shared.global [%0], [%1], 16;\n" :: "r"(sv), "l"(gv));
        }
        asm volatile("cp.async.commit_group;\n");
    };

    issueKV(0, cs0);
    if (n_chunks > 1) issueKV(1, cs0 + 64);

    // Q staging overlaps the in-flight cp.async
    {
        int q = tid >> 1, half_sel = tid & 1;
        const __half2 s2 = __floats2half2_rn(0.125f, 0.125f);
#pragma unroll
        for (int v = 0; v < 4; v++) {
            int c8 = half_sel * 32 + v * 8;
            uint2 raw = *(const uint2*)(Qg + (size_t)(i0 + q) * HD + c8);
            __half2 h0 = __hmul2(*(__half2*)&raw.x, s2);
            __half2 h1 = __hmul2(*(__half2*)&raw.y, s2);
            uint2 raw2 = *(const uint2*)(Qg + (size_t)(i0 + q) * HD + c8 + 4);
            __half2 h2 = __hmul2(*(__half2*)&raw2.x, s2);
            __half2 h3 = __hmul2(*(__half2*)&raw2.y, s2);
            __half* dst = Qs + q * AST + c8;
            *(__half2*)(dst)     = h0;
            *(__half2*)(dst + 2) = h1;
            *(__half2*)(dst + 4) = h2;
            *(__half2*)(dst + 6) = h3;
        }
    }

    int iq0 = i0 + rbase + g;
    int iq1 = iq0 + 8;

    float m0 = -1e30f, m1 = -1e30f, l0 = 0.f, l1 = 0.f;
    float oacc[8][4];
#pragma unroll
    for (int nt = 0; nt < 8; nt++)
#pragma unroll
        for (int i = 0; i < 4; i++) oacc[nt][i] = 0.f;

    int stage = 0, fill = 2;

    for (int ci = 0; ci < n_chunks; ci++) {
        int cs = cs0 + ci * 64;
        if (ci < n_chunks - 1) asm volatile("cp.async.wait_group 1;\n" ::: "memory");
        else                   asm volatile("cp.async.wait_group 0;\n" ::: "memory");
        // Single barrier: chunk ci visible to all; all warps done reading 'fill'
        __syncthreads();

        if (ci + 2 < n_chunks) issueKV(fill, cs + 128);

        unsigned shK_st = shKV + stage * ATT_STG_BYTES;
        unsigned shV_st = shK_st + 64 * AST * 2;

        // S = Q*K^T
        float sacc[8][4];
#pragma unroll
        for (int nt = 0; nt < 8; nt++)
#pragma unroll
            for (int i = 0; i < 4; i++) sacc[nt][i] = 0.f;

#pragma unroll
        for (int kk = 0; kk < 4; kk++) {
            int c = kk * 16;
            unsigned af[4], bf[4][4];
            ldsm_x4(af, shQ + (unsigned)(a_off + c) * 2);
#pragma unroll
            for (int p = 0; p < 4; p++)
                ldsm_x4(bf[p], shK_st + (unsigned)(b_off + p * 16 * AST + c) * 2);
#pragma unroll
            for (int nt = 0; nt < 8; nt++)
                mma_f16(sacc[nt], af, &bf[nt >> 1][(nt & 1) * 2]);
        }

        // Mask + online softmax
        float rmax0 = -1e30f, rmax1 = -1e30f;
#pragma unroll
        for (int nt = 0; nt < 8; nt++) {
#pragma unroll
            for (int e = 0; e < 2; e++) {
                int j = cs + nt * 8 + 2 * t + e;
                if (!((j <= iq0) && (j > iq0 - WIN))) sacc[nt][e] = -1e30f;
                if (!((j <= iq1) && (j > iq1 - WIN))) sacc[nt][2 + e] = -1e30f;
                rmax0 = fmaxf(rmax0, sacc[nt][e]);
                rmax1 = fmaxf(rmax1, sacc[nt][2 + e]);
            }
        }
#pragma unroll
        for (int msk = 1; msk < 4; msk <<= 1) {
            rmax0 = fmaxf(rmax0, __shfl_xor_sync(0xffffffffu, rmax0, msk));
            rmax1 = fmaxf(rmax1, __shfl_xor_sync(0xffffffffu, rmax1, msk));
        }

        float mn0 = fmaxf(m0, rmax0);
        float mn1 = fmaxf(m1, rmax1);
        float cor0 = __expf(m0 - mn0);
        float cor1 = __expf(m1 - mn1);
        m0 = mn0; m1 = mn1;

        float rs0 = 0.f, rs1 = 0.f;
#pragma unroll
        for (int nt = 0; nt < 8; nt++) {
            float p0 = __expf(sacc[nt][0] - mn0);
            float p1 = __expf(sacc[nt][1] - mn0);
            float p2 = __expf(sacc[nt][2] - mn1);
            float p3 = __expf(sacc[nt][3] - mn1);
            rs0 += p0 + p1;
            rs1 += p2 + p3;
            int col = nt * 8 + 2 * t;
            *(__half2*)(Ps + (rbase + g) * AST + col)     = __floats2half2_rn(p0, p1);
            *(__half2*)(Ps + (rbase + g + 8) * AST + col) = __floats2half2_rn(p2, p3);
        }
#pragma unroll
        for (int msk = 1; msk < 4; msk <<= 1) {
            rs0 += __shfl_xor_sync(0xffffffffu, rs0, msk);
            rs1 += __shfl_xor_sync(0xffffffffu, rs1, msk);
        }
        l0 = l0 * cor0 + rs0;
        l1 = l1 * cor1 + rs1;
#pragma unroll
        for (int nt = 0; nt < 8; nt++) {
            oacc[nt][0] *= cor0; oacc[nt][1] *= cor0;
            oacc[nt][2] *= cor1; oacc[nt][3] *= cor1;
        }
        __syncwarp();

        // O += P * V (B fragments via ldmatrix.trans from natural-layout V)
#pragma unroll
        for (int kk = 0; kk < 4; kk++) {
            int c = kk * 16;
            unsigned af[4], bf[4][4];
            ldsm_x4(af, shP + (unsigned)(a_off + c) * 2);
#pragma unroll
            for (int p = 0; p < 4; p++)
                ldsm_x4_trans(bf[p], shV_st + (unsigned)(vb_off + c * AST + p * 16) * 2);
#pragma unroll
            for (int nt = 0; nt < 8; nt++)
                mma_f16(oacc[nt], af, &bf[nt >> 1][(nt & 1) * 2]);
        }

        fill  = stage;
        stage = (stage == 2) ? 0 : stage + 1;
    }

    // Normalize + write fp16 O
    float inv0 = 1.f / l0;
    float inv1 = 1.f / l1;
    int b = bh / NHEADS;
    int h = bh % NHEADS;
    __half* O0 = g_O + (size_t)(b * SEQ + iq0) * D_MODEL + h * HD;
    __half* O1 = g_O + (size_t)(b * SEQ + iq1) * D_MODEL + h * HD;
#pragma unroll
    for (int nt = 0; nt < 8; nt++) {
        int d = nt * 8 + 2 * t;
        *(__half2*)(O0 + d) = __floats2half2_rn(oacc[nt][0] * inv0, oacc[nt][1] * inv0);
        *(__half2*)(O1 + d) = __floats2half2_rn(oacc[nt][2] * inv1, oacc[nt][3] * inv1);
    }
}

// ---------------------------------------------------------------------------
extern "C" void kernel_launch(void* const* d_in, const int* in_sizes, int n_in,
                              void* d_out, int out_size)
{
    const float* x  = (const float*)d_in[0];
    const float* w1 = (const float*)d_in[1];
    const float* b1 = (const float*)d_in[2];
    const float* w2 = (const float*)d_in[3];
    const float* b2 = (const float*)d_in[4];
    float* out = (float*)d_out;

    const int M = BATCH * SEQ;

    __half *cx, *cw1, *cw2;
    cudaGetSymbolAddress((void**)&cx,  c_x);
    cudaGetSymbolAddress((void**)&cw1, c_w1);
    cudaGetSymbolAddress((void**)&cw2, c_w2);

    // 0) fused fp32 -> fp16 conversion (single launch)
    {
        int n4x  = M * D_MODEL / 4;
        int n4w1 = 3 * D_MODEL * D_MODEL / 4;
        int n4w2 = D_MODEL * D_MODEL / 4;
        int total = n4x + n4w1 + n4w2;
        cvt_all<<<(total + 255) / 256, 256>>>((const float4*)x, (uint2*)cx, n4x,
                                              (const float4*)w1, (uint2*)cw1, n4w1,
                                              (const float4*)w2, (uint2*)cw2, n4w2);
    }

    const int gemm_smem = 2 * NSTG * STG_BYTES;   // 110592 B

    // 1) QKV projection (fp16 mma, R9 config)
    {
        cudaFuncSetAttribute(gemm_f16<0>,
                             cudaFuncAttributeMaxDynamicSharedMemorySize, gemm_smem);
        dim3 grid(3 * D_MODEL / 128, M / 128);
        gemm_f16<0><<<grid, 256, gemm_smem>>>(cx, cw1, b1, nullptr, M, 3 * D_MODEL, D_MODEL);
    }

    // 2) Sliding-window attention (fp16 mma, 3-stage cp.async K/V pipeline)
    {
        int smem = (64 * AST + 3 * ATT_STG_HALVES + 64 * AST) * (int)sizeof(__half); // 73728
        cudaFuncSetAttribute(attn_mma,
                             cudaFuncAttributeMaxDynamicSharedMemorySize, smem);
        dim3 grid(SEQ / 64, BATCH * NHEADS);
        attn_mma<<<grid, 128, smem>>>();
    }

    // 3) Output projection (fp16 mma, R9 config)
    {
        cudaFuncSetAttribute(gemm_f16<1>,
                             cudaFuncAttributeMaxDynamicSharedMemorySize, gemm_smem);
        dim3 grid(D_MODEL / 128, M / 128);
        gemm_f16<1><<<grid, 256, gemm_smem>>>(nullptr, cw2, b2, out, M, D_MODEL, D_MODEL);
    }
}

// round 14
// speedup vs baseline: 1.1892x; 1.0567x over previous
#include <cuda_runtime.h>
#include <cuda_fp16.h>
#include <math.h>
#include <stdint.h>

#define D_MODEL 1024
#define NHEADS  16
#define HD      64
#define SEQ     2048
#define BATCH   2
#define WIN     256

// Scratch (allocation-free: __device__ globals). All fp16.
__device__ __half g_Q[BATCH * NHEADS * SEQ * HD];   // [b][h][l][d]
__device__ __half g_K[BATCH * NHEADS * SEQ * HD];
__device__ __half g_V[BATCH * NHEADS * SEQ * HD];
__device__ __half g_O[BATCH * SEQ * D_MODEL];       // [b][l][h*64+d]
__device__ __half c_x [BATCH * SEQ * D_MODEL];
__device__ __half c_w1[3 * D_MODEL * D_MODEL];
__device__ __half c_w2[D_MODEL * D_MODEL];

__device__ __forceinline__ void mma_f16(float c[4], const unsigned a[4], const unsigned b[2]) {
    asm volatile(
        "mma.sync.aligned.m16n8k16.row.col.f32.f16.f16.f32 "
        "{%0,%1,%2,%3}, {%4,%5,%6,%7}, {%8,%9}, {%0,%1,%2,%3};\n"
        : "+f"(c[0]), "+f"(c[1]), "+f"(c[2]), "+f"(c[3])
        : "r"(a[0]), "r"(a[1]), "r"(a[2]), "r"(a[3]),
          "r"(b[0]), "r"(b[1]));
}

__device__ __forceinline__ void ldsm_x4(unsigned a[4], unsigned saddr) {
    asm volatile("ldmatrix.sync.aligned.m8n8.x4.shared.b16 {%0,%1,%2,%3}, [%4];"
        : "=r"(a[0]), "=r"(a[1]), "=r"(a[2]), "=r"(a[3]) : "r"(saddr));
}

__device__ __forceinline__ void ldsm_x4_trans(unsigned a[4], unsigned saddr) {
    asm volatile("ldmatrix.sync.aligned.m8n8.x4.trans.shared.b16 {%0,%1,%2,%3}, [%4];"
        : "=r"(a[0]), "=r"(a[1]), "=r"(a[2]), "=r"(a[3]) : "r"(saddr));
}

// ---------------------------------------------------------------------------
// Fused fp32 -> fp16 bulk converter for x, w1, w2 (one launch)
// ---------------------------------------------------------------------------
__global__ void cvt_all(const float4* __restrict__ x,  uint2* __restrict__ cx,  int n4x,
                        const float4* __restrict__ w1, uint2* __restrict__ cw1, int n4w1,
                        const float4* __restrict__ w2, uint2* __restrict__ cw2, int n4w2)
{
    int i = blockIdx.x * blockDim.x + threadIdx.x;
    const float4* src;
    uint2* dst;
    int idx;
    if (i < n4x)                   { src = x;  dst = cx;  idx = i; }
    else if (i < n4x + n4w1)       { src = w1; dst = cw1; idx = i - n4x; }
    else if (i < n4x + n4w1 + n4w2){ src = w2; dst = cw2; idx = i - n4x - n4w1; }
    else return;
    float4 v = src[idx];
    __half2 h01 = __floats2half2_rn(v.x, v.y);
    __half2 h23 = __floats2half2_rn(v.z, v.w);
    uint2 u;
    u.x = *(unsigned*)&h01;
    u.y = *(unsigned*)&h23;
    dst[idx] = u;
}

// ---------------------------------------------------------------------------
// Persistent FP16 NT GEMM (fp32 accum), BK=64, 3-stage cp.async pipeline.
// Each CTA owns NSUB N-adjacent 128x128 tiles; ONE unified pipeline streams
// across sub-tile boundaries (no drain). Grid = (M/128)*(N/(128*NSUB)) CTAs.
// MODE 0: A=c_x -> scatter g_Q/K/V.  MODE 1: A=g_O -> Cout.
// ---------------------------------------------------------------------------
#define SSTR 72
#define BK   64
#define STG_HALVES (128 * SSTR)
#define STG_BYTES  (STG_HALVES * 2)
#define NSTG 3

template <int MODE, int NSUB>
__global__ __launch_bounds__(256, 2)
void gemm_f16(const __half* __restrict__ A, const __half* __restrict__ W,
              const float* __restrict__ bias, float* __restrict__ Cout,
              int M, int N, int K)
{
    extern __shared__ __half sh[];
    __half* AsBase = sh;
    __half* BsBase = sh + NSTG * STG_HALVES;

    const __half* Ap = (MODE == 1) ? (const __half*)g_O : A;

    int tid  = threadIdx.x;
    int lane = tid & 31;
    int wid  = tid >> 5;
    int wm = (wid >> 2) * 64;
    int wn = (wid & 3) * 32;
    int bx = blockIdx.x;
    int bm      = (bx >> 3) * 128;               // 32 m-rows
    int bn_base = (bx & 7) * (NSUB * 128);       // 8 n-groups of NSUB tiles
    int g = lane >> 2;
    int t = lane & 3;
    int lr = lane & 7;

    int a_off = (wm + lr + (((lane >> 3) & 1) ? 8 : 0)) * SSTR + ((lane >> 4) ? 8 : 0);
    int b_off = (wn + lr + ((lane >> 4) ? 8 : 0)) * SSTR + (((lane >> 3) & 1) ? 8 : 0);

    unsigned shA = (unsigned)__cvta_generic_to_shared(AsBase);
    unsigned shB = (unsigned)__cvta_generic_to_shared(BsBase);

    float acc[4][4][4];
#pragma unroll
    for (int mt = 0; mt < 4; mt++)
#pragma unroll
        for (int nt = 0; nt < 4; nt++)
#pragma unroll
            for (int i = 0; i < 4; i++) acc[mt][nt][i] = 0.f;

    const int KT = K / BK;            // k-tiles per sub-tile (16)
    const int TOTAL = KT * NSUB;      // unified pipeline length

    // stage fill for unified tile index tt
    auto issue = [&](int s, int tt) {
        int sub = tt / KT;
        int k0  = (tt - sub * KT) * BK;
        int bn  = bn_base + sub * 128;
        __half* dA = AsBase + s * STG_HALVES;
        __half* dB = BsBase + s * STG_HALVES;
#pragma unroll
        for (int r = 0; r < 4; r++) {
            int id  = tid + r * 256;
            int row = id >> 3;
            int c   = id & 7;
            const __half* ga = Ap + (size_t)(bm + row) * K + k0 + c * 8;
            const __half* gb = W  + (size_t)(bn + row) * K + k0 + c * 8;
            unsigned sa = (unsigned)__cvta_generic_to_shared(dA + row * SSTR + c * 8);
            unsigned sb = (unsigned)__cvta_generic_to_shared(dB + row * SSTR + c * 8);
            asm volatile("cp.async.cg.shared.global [%0], [%1], 16;\n" :: "r"(sa), "l"(ga));
            asm volatile("cp.async.cg.shared.global [%0], [%1], 16;\n" :: "r"(sb), "l"(gb));
        }
        asm volatile("cp.async.commit_group;\n");
    };

    issue(0, 0);
    issue(1, 1);

    int stage = 0, fill = 2;
    int kc = 0, sub = 0;

    for (int tt = 0; tt < TOTAL; tt++) {
        if (tt + 1 < TOTAL) asm volatile("cp.async.wait_group 1;\n" ::: "memory");
        else                asm volatile("cp.async.wait_group 0;\n" ::: "memory");
        __syncthreads();

        if (tt + 2 < TOTAL) issue(fill, tt + 2);

        unsigned stA = shA + stage * STG_BYTES;
        unsigned stB = shB + stage * STG_BYTES;

#pragma unroll
        for (int ks = 0; ks < 4; ks++) {
            int kk = ks * 16;
            unsigned af[4][4], bf[2][4];
#pragma unroll
            for (int mt = 0; mt < 4; mt++)
                ldsm_x4(af[mt], stA + (unsigned)(a_off + mt * 16 * SSTR + kk) * 2);
#pragma unroll
            for (int p = 0; p < 2; p++)
                ldsm_x4(bf[p], stB + (unsigned)(b_off + p * 16 * SSTR + kk) * 2);
#pragma unroll
            for (int mt = 0; mt < 4; mt++)
#pragma unroll
                for (int nt = 0; nt < 4; nt++)
                    mma_f16(acc[mt][nt], af[mt], &bf[nt >> 1][(nt & 1) * 2]);
        }

        fill  = stage;
        stage = (stage == 2) ? 0 : stage + 1;

        // Sub-tile complete -> epilogue (register-only; overlaps in-flight loads)
        if (++kc == KT) {
            kc = 0;
            int bn = bn_base + sub * 128;
#pragma unroll
            for (int mt = 0; mt < 4; mt++) {
#pragma unroll
                for (int nt = 0; nt < 4; nt++) {
#pragma unroll
                    for (int h2 = 0; h2 < 2; h2++) {
                        int m = bm + wm + mt * 16 + g + (h2 ? 8 : 0);
                        int n = bn + wn + nt * 8 + t * 2;
                        float v0 = acc[mt][nt][h2 * 2 + 0] + bias[n];
                        float v1 = acc[mt][nt][h2 * 2 + 1] + bias[n + 1];
                        if (MODE == 0) {
                            int part   = n >> 10;
                            int within = n & 1023;
                            int h = within >> 6;
                            int d = within & 63;     // even -> d,d+1 same head
                            int b = m >> 11;
                            int l = m & 2047;
                            size_t dst = ((size_t)(b * NHEADS + h) * SEQ + l) * HD + d;
                            __half* base = (part == 0) ? g_Q : (part == 1) ? g_K : g_V;
                            *(__half2*)(base + dst) = __floats2half2_rn(v0, v1);
                        } else {
                            float2 fv = make_float2(v0, v1);
                            *(float2*)(&Cout[(size_t)m * N + n]) = fv;
                        }
                        acc[mt][nt][h2 * 2 + 0] = 0.f;
                        acc[mt][nt][h2 * 2 + 1] = 0.f;
                    }
                }
            }
            sub++;
        }
    }
}

// ---------------------------------------------------------------------------
// Sliding-window attention, fp16 mma + ldmatrix + 3-stage cp.async K/V pipeline.
// (unchanged from R13)
// ---------------------------------------------------------------------------
#define AST 72
#define ATT_STG_HALVES (2 * 64 * AST)
#define ATT_STG_BYTES  (ATT_STG_HALVES * 2)

__global__ __launch_bounds__(128)
void attn_mma()
{
    extern __shared__ __half smh[];
    __half* Qs     = smh;
    __half* KVbase = smh + 64 * AST;
    __half* Ps     = KVbase + 3 * ATT_STG_HALVES;

    int tid  = threadIdx.x;
    int lane = tid & 31;
    int wid  = tid >> 5;
    int g = lane >> 2;
    int t = lane & 3;
    int lr = lane & 7;

    int bh = blockIdx.y;
    int i0 = blockIdx.x * 64;

    const __half* Qg = g_Q + (size_t)bh * SEQ * HD;
    const __half* Kg = g_K + (size_t)bh * SEQ * HD;
    const __half* Vg = g_V + (size_t)bh * SEQ * HD;

    int rbase = wid * 16;
    int a_off = (rbase + lr + (((lane >> 3) & 1) ? 8 : 0)) * AST + ((lane >> 4) ? 8 : 0);
    int b_off = (lr + ((lane >> 4) ? 8 : 0)) * AST + (((lane >> 3) & 1) ? 8 : 0);
    int vb_off = (lr + (((lane >> 3) & 1) ? 8 : 0)) * AST + ((lane >> 4) ? 8 : 0);

    unsigned shQ  = (unsigned)__cvta_generic_to_shared(Qs);
    unsigned shKV = (unsigned)__cvta_generic_to_shared(KVbase);
    unsigned shP  = (unsigned)__cvta_generic_to_shared(Ps);

    int kv_lo = i0 - (WIN - 1);
    if (kv_lo < 0) kv_lo = 0;
    int cs0 = (kv_lo / 64) * 64;
    int n_chunks = (i0 - cs0) / 64 + 1;

    auto issueKV = [&](int s, int cs) {
        __half* dK = KVbase + s * ATT_STG_HALVES;
        __half* dV = dK + 64 * AST;
#pragma unroll
        for (int r = 0; r < 4; r++) {
            int id  = tid + r * 128;
            int row = id >> 3;
            int c   = id & 7;
            const __half* gk = Kg + (size_t)(cs + row) * HD + c * 8;
            const __half* gv = Vg + (size_t)(cs + row) * HD + c * 8;
            unsigned sk = (unsigned)__cvta_generic_to_shared(dK + row * AST + c * 8);
            unsigned sv = (unsigned)__cvta_generic_to_shared(dV + row * AST + c * 8);
            asm volatile("cp.async.cg.shared.global [%0], [%1], 16;\n" :: "r"(sk), "l"(gk));
            asm volatile("cp.async.cg.shared.global [%0], [%1], 16;\n" :: "r"(sv), "l"(gv));
        }
        asm volatile("cp.async.commit_group;\n");
    };

    issueKV(0, cs0);
    if (n_chunks > 1) issueKV(1, cs0 + 64);

    {
        int q = tid >> 1, half_sel = tid & 1;
        const __half2 s2 = __floats2half2_rn(0.125f, 0.125f);
#pragma unroll
        for (int v = 0; v < 4; v++) {
            int c8 = half_sel * 32 + v * 8;
            uint2 raw = *(const uint2*)(Qg + (size_t)(i0 + q) * HD + c8);
            __half2 h0 = __hmul2(*(__half2*)&raw.x, s2);
            __half2 h1 = __hmul2(*(__half2*)&raw.y, s2);
            uint2 raw2 = *(const uint2*)(Qg + (size_t)(i0 + q) * HD + c8 + 4);
            __half2 h2 = __hmul2(*(__half2*)&raw2.x, s2);
            __half2 h3 = __hmul2(*(__half2*)&raw2.y, s2);
            __half* dst = Qs + q * AST + c8;
            *(__half2*)(dst)     = h0;
            *(__half2*)(dst + 2) = h1;
            *(__half2*)(dst + 4) = h2;
            *(__half2*)(dst + 6) = h3;
        }
    }

    int iq0 = i0 + rbase + g;
    int iq1 = iq0 + 8;

    float m0 = -1e30f, m1 = -1e30f, l0 = 0.f, l1 = 0.f;
    float oacc[8][4];
#pragma unroll
    for (int nt = 0; nt < 8; nt++)
#pragma unroll
        for (int i = 0; i < 4; i++) oacc[nt][i] = 0.f;

    int stage = 0, fill = 2;

    for (int ci = 0; ci < n_chunks; ci++) {
        int cs = cs0 + ci * 64;
        if (ci < n_chunks - 1) asm volatile("cp.async.wait_group 1;\n" ::: "memory");
        else                   asm volatile("cp.async.wait_group 0;\n" ::: "memory");
        __syncthreads();

        if (ci + 2 < n_chunks) issueKV(fill, cs + 128);

        unsigned shK_st = shKV + stage * ATT_STG_BYTES;
        unsigned shV_st = shK_st + 64 * AST * 2;

        float sacc[8][4];
#pragma unroll
        for (int nt = 0; nt < 8; nt++)
#pragma unroll
            for (int i = 0; i < 4; i++) sacc[nt][i] = 0.f;

#pragma unroll
        for (int kk = 0; kk < 4; kk++) {
            int c = kk * 16;
            unsigned af[4], bf[4][4];
            ldsm_x4(af, shQ + (unsigned)(a_off + c) * 2);
#pragma unroll
            for (int p = 0; p < 4; p++)
                ldsm_x4(bf[p], shK_st + (unsigned)(b_off + p * 16 * AST + c) * 2);
#pragma unroll
            for (int nt = 0; nt < 8; nt++)
                mma_f16(sacc[nt], af, &bf[nt >> 1][(nt & 1) * 2]);
        }

        float rmax0 = -1e30f, rmax1 = -1e30f;
#pragma unroll
        for (int nt = 0; nt < 8; nt++) {
#pragma unroll
            for (int e = 0; e < 2; e++) {
                int j = cs + nt * 8 + 2 * t + e;
                if (!((j <= iq0) && (j > iq0 - WIN))) sacc[nt][e] = -1e30f;
                if (!((j <= iq1) && (j > iq1 - WIN))) sacc[nt][2 + e] = -1e30f;
                rmax0 = fmaxf(rmax0, sacc[nt][e]);
                rmax1 = fmaxf(rmax1, sacc[nt][2 + e]);
            }
        }
#pragma unroll
        for (int msk = 1; msk < 4; msk <<= 1) {
            rmax0 = fmaxf(rmax0, __shfl_xor_sync(0xffffffffu, rmax0, msk));
            rmax1 = fmaxf(rmax1, __shfl_xor_sync(0xffffffffu, rmax1, msk));
        }

        float mn0 = fmaxf(m0, rmax0);
        float mn1 = fmaxf(m1, rmax1);
        float cor0 = __expf(m0 - mn0);
        float cor1 = __expf(m1 - mn1);
        m0 = mn0; m1 = mn1;

        float rs0 = 0.f, rs1 = 0.f;
#pragma unroll
        for (int nt = 0; nt < 8; nt++) {
            float p0 = __expf(sacc[nt][0] - mn0);
            float p1 = __expf(sacc[nt][1] - mn0);
            float p2 = __expf(sacc[nt][2] - mn1);
            float p3 = __expf(sacc[nt][3] - mn1);
            rs0 += p0 + p1;
            rs1 += p2 + p3;
            int col = nt * 8 + 2 * t;
            *(__half2*)(Ps + (rbase + g) * AST + col)     = __floats2half2_rn(p0, p1);
            *(__half2*)(Ps + (rbase + g + 8) * AST + col) = __floats2half2_rn(p2, p3);
        }
#pragma unroll
        for (int msk = 1; msk < 4; msk <<= 1) {
            rs0 += __shfl_xor_sync(0xffffffffu, rs0, msk);
            rs1 += __shfl_xor_sync(0xffffffffu, rs1, msk);
        }
        l0 = l0 * cor0 + rs0;
        l1 = l1 * cor1 + rs1;
#pragma unroll
        for (int nt = 0; nt < 8; nt++) {
            oacc[nt][0] *= cor0; oacc[nt][1] *= cor0;
            oacc[nt][2] *= cor1; oacc[nt][3] *= cor1;
        }
        __syncwarp();

#pragma unroll
        for (int kk = 0; kk < 4; kk++) {
            int c = kk * 16;
            unsigned af[4], bf[4][4];
            ldsm_x4(af, shP + (unsigned)(a_off + c) * 2);
#pragma unroll
            for (int p = 0; p < 4; p++)
                ldsm_x4_trans(bf[p], shV_st + (unsigned)(vb_off + c * AST + p * 16) * 2);
#pragma unroll
            for (int nt = 0; nt < 8; nt++)
                mma_f16(oacc[nt], af, &bf[nt >> 1][(nt & 1) * 2]);
        }

        fill  = stage;
        stage = (stage == 2) ? 0 : stage + 1;
    }

    float inv0 = 1.f / l0;
    float inv1 = 1.f / l1;
    int b = bh / NHEADS;
    int h = bh % NHEADS;
    __half* O0 = g_O + (size_t)(b * SEQ + iq0) * D_MODEL + h * HD;
    __half* O1 = g_O + (size_t)(b * SEQ + iq1) * D_MODEL + h * HD;
#pragma unroll
    for (int nt = 0; nt < 8; nt++) {
        int d = nt * 8 + 2 * t;
        *(__half2*)(O0 + d) = __floats2half2_rn(oacc[nt][0] * inv0, oacc[nt][1] * inv0);
        *(__half2*)(O1 + d) = __floats2half2_rn(oacc[nt][2] * inv1, oacc[nt][3] * inv1);
    }
}

// ---------------------------------------------------------------------------
extern "C" void kernel_launch(void* const* d_in, const int* in_sizes, int n_in,
                              void* d_out, int out_size)
{
    const float* x  = (const float*)d_in[0];
    const float* w1 = (const float*)d_in[1];
    const float* b1 = (const float*)d_in[2];
    const float* w2 = (const float*)d_in[3];
    const float* b2 = (const float*)d_in[4];
    float* out = (float*)d_out;

    const int M = BATCH * SEQ;

    __half *cx, *cw1, *cw2;
    cudaGetSymbolAddress((void**)&cx,  c_x);
    cudaGetSymbolAddress((void**)&cw1, c_w1);
    cudaGetSymbolAddress((void**)&cw2, c_w2);

    // 0) fused fp32 -> fp16 conversion (single launch)
    {
        int n4x  = M * D_MODEL / 4;
        int n4w1 = 3 * D_MODEL * D_MODEL / 4;
        int n4w2 = D_MODEL * D_MODEL / 4;
        int total = n4x + n4w1 + n4w2;
        cvt_all<<<(total + 255) / 256, 256>>>((const float4*)x, (uint2*)cx, n4x,
                                              (const float4*)w1, (uint2*)cw1, n4w1,
                                              (const float4*)w2, (uint2*)cw2, n4w2);
    }

    const int gemm_smem = 2 * NSTG * STG_BYTES;   // 110592 B

    // 1) QKV projection: persistent, 256 CTAs x 3 tiles (768 = 256*3, zero tail)
    {
        cudaFuncSetAttribute(gemm_f16<0, 3>,
                             cudaFuncAttributeMaxDynamicSharedMemorySize, gemm_smem);
        gemm_f16<0, 3><<<256, 256, gemm_smem>>>(cx, cw1, b1, nullptr,
                                                M, 3 * D_MODEL, D_MODEL);
    }

    // 2) Sliding-window attention (fp16 mma, 3-stage cp.async K/V pipeline)
    {
        int smem = (64 * AST + 3 * ATT_STG_HALVES + 64 * AST) * (int)sizeof(__half);
        cudaFuncSetAttribute(attn_mma,
                             cudaFuncAttributeMaxDynamicSharedMemorySize, smem);
        dim3 grid(SEQ / 64, BATCH * NHEADS);
        attn_mma<<<grid, 128, smem>>>();
    }

    // 3) Output projection: 256 CTAs x 1 tile (single wave)
    {
        cudaFuncSetAttribute(gemm_f16<1, 1>,
                             cudaFuncAttributeMaxDynamicSharedMemorySize, gemm_smem);
        gemm_f16<1, 1><<<256, 256, gemm_smem>>>(nullptr, cw2, b2, out,
                                                M, D_MODEL, D_MODEL);
    }
}

// round 15
// speedup vs baseline: 1.2027x; 1.0113x over previous
#include <cuda_runtime.h>
#include <cuda_fp16.h>
#include <math.h>
#include <stdint.h>

#define D_MODEL 1024
#define NHEADS  16
#define HD      64
#define SEQ     2048
#define BATCH   2
#define WIN     256

// Scratch (allocation-free: __device__ globals). All fp16.
__device__ __half g_Q[BATCH * NHEADS * SEQ * HD];   // [b][h][l][d]
__device__ __half g_K[BATCH * NHEADS * SEQ * HD];
__device__ __half g_V[BATCH * NHEADS * SEQ * HD];
__device__ __half g_O[BATCH * SEQ * D_MODEL];       // [b][l][h*64+d]
__device__ __half c_x [BATCH * SEQ * D_MODEL];
__device__ __half c_w1[3 * D_MODEL * D_MODEL];
__device__ __half c_w2[D_MODEL * D_MODEL];

__device__ __forceinline__ void mma_f16(float c[4], const unsigned a[4], const unsigned b[2]) {
    asm volatile(
        "mma.sync.aligned.m16n8k16.row.col.f32.f16.f16.f32 "
        "{%0,%1,%2,%3}, {%4,%5,%6,%7}, {%8,%9}, {%0,%1,%2,%3};\n"
        : "+f"(c[0]), "+f"(c[1]), "+f"(c[2]), "+f"(c[3])
        : "r"(a[0]), "r"(a[1]), "r"(a[2]), "r"(a[3]),
          "r"(b[0]), "r"(b[1]));
}

__device__ __forceinline__ void ldsm_x4(unsigned a[4], unsigned saddr) {
    asm volatile("ldmatrix.sync.aligned.m8n8.x4.shared.b16 {%0,%1,%2,%3}, [%4];"
        : "=r"(a[0]), "=r"(a[1]), "=r"(a[2]), "=r"(a[3]) : "r"(saddr));
}

__device__ __forceinline__ void ldsm_x4_trans(unsigned a[4], unsigned saddr) {
    asm volatile("ldmatrix.sync.aligned.m8n8.x4.trans.shared.b16 {%0,%1,%2,%3}, [%4];"
        : "=r"(a[0]), "=r"(a[1]), "=r"(a[2]), "=r"(a[3]) : "r"(saddr));
}

// ---------------------------------------------------------------------------
// Fused fp32 -> fp16 bulk converter for x, w1, w2 (one launch)
// ---------------------------------------------------------------------------
__global__ void cvt_all(const float4* __restrict__ x,  uint2* __restrict__ cx,  int n4x,
                        const float4* __restrict__ w1, uint2* __restrict__ cw1, int n4w1,
                        const float4* __restrict__ w2, uint2* __restrict__ cw2, int n4w2)
{
    int i = blockIdx.x * blockDim.x + threadIdx.x;
    const float4* src;
    uint2* dst;
    int idx;
    if (i < n4x)                   { src = x;  dst = cx;  idx = i; }
    else if (i < n4x + n4w1)       { src = w1; dst = cw1; idx = i - n4x; }
    else if (i < n4x + n4w1 + n4w2){ src = w2; dst = cw2; idx = i - n4x - n4w1; }
    else return;
    float4 v = src[idx];
    __half2 h01 = __floats2half2_rn(v.x, v.y);
    __half2 h23 = __floats2half2_rn(v.z, v.w);
    uint2 u;
    u.x = *(unsigned*)&h01;
    u.y = *(unsigned*)&h23;
    dst[idx] = u;
}

// ---------------------------------------------------------------------------
// Persistent FP16 NT GEMM (fp32 accum), BK=64, 3-stage cp.async pipeline.
// (unchanged from R14 — at legacy-HMMA issue ceiling)
// ---------------------------------------------------------------------------
#define SSTR 72
#define BK   64
#define STG_HALVES (128 * SSTR)
#define STG_BYTES  (STG_HALVES * 2)
#define NSTG 3

template <int MODE, int NSUB>
__global__ __launch_bounds__(256, 2)
void gemm_f16(const __half* __restrict__ A, const __half* __restrict__ W,
              const float* __restrict__ bias, float* __restrict__ Cout,
              int M, int N, int K)
{
    extern __shared__ __half sh[];
    __half* AsBase = sh;
    __half* BsBase = sh + NSTG * STG_HALVES;

    const __half* Ap = (MODE == 1) ? (const __half*)g_O : A;

    int tid  = threadIdx.x;
    int lane = tid & 31;
    int wid  = tid >> 5;
    int wm = (wid >> 2) * 64;
    int wn = (wid & 3) * 32;
    int bx = blockIdx.x;
    int bm      = (bx >> 3) * 128;
    int bn_base = (bx & 7) * (NSUB * 128);
    int g = lane >> 2;
    int t = lane & 3;
    int lr = lane & 7;

    int a_off = (wm + lr + (((lane >> 3) & 1) ? 8 : 0)) * SSTR + ((lane >> 4) ? 8 : 0);
    int b_off = (wn + lr + ((lane >> 4) ? 8 : 0)) * SSTR + (((lane >> 3) & 1) ? 8 : 0);

    unsigned shA = (unsigned)__cvta_generic_to_shared(AsBase);
    unsigned shB = (unsigned)__cvta_generic_to_shared(BsBase);

    float acc[4][4][4];
#pragma unroll
    for (int mt = 0; mt < 4; mt++)
#pragma unroll
        for (int nt = 0; nt < 4; nt++)
#pragma unroll
            for (int i = 0; i < 4; i++) acc[mt][nt][i] = 0.f;

    const int KT = K / BK;
    const int TOTAL = KT * NSUB;

    auto issue = [&](int s, int tt) {
        int sub = tt / KT;
        int k0  = (tt - sub * KT) * BK;
        int bn  = bn_base + sub * 128;
        __half* dA = AsBase + s * STG_HALVES;
        __half* dB = BsBase + s * STG_HALVES;
#pragma unroll
        for (int r = 0; r < 4; r++) {
            int id  = tid + r * 256;
            int row = id >> 3;
            int c   = id & 7;
            const __half* ga = Ap + (size_t)(bm + row) * K + k0 + c * 8;
            const __half* gb = W  + (size_t)(bn + row) * K + k0 + c * 8;
            unsigned sa = (unsigned)__cvta_generic_to_shared(dA + row * SSTR + c * 8);
            unsigned sb = (unsigned)__cvta_generic_to_shared(dB + row * SSTR + c * 8);
            asm volatile("cp.async.cg.shared.global [%0], [%1], 16;\n" :: "r"(sa), "l"(ga));
            asm volatile("cp.async.cg.shared.global [%0], [%1], 16;\n" :: "r"(sb), "l"(gb));
        }
        asm volatile("cp.async.commit_group;\n");
    };

    issue(0, 0);
    issue(1, 1);

    int stage = 0, fill = 2;
    int kc = 0, sub = 0;

    for (int tt = 0; tt < TOTAL; tt++) {
        if (tt + 1 < TOTAL) asm volatile("cp.async.wait_group 1;\n" ::: "memory");
        else                asm volatile("cp.async.wait_group 0;\n" ::: "memory");
        __syncthreads();

        if (tt + 2 < TOTAL) issue(fill, tt + 2);

        unsigned stA = shA + stage * STG_BYTES;
        unsigned stB = shB + stage * STG_BYTES;

#pragma unroll
        for (int ks = 0; ks < 4; ks++) {
            int kk = ks * 16;
            unsigned af[4][4], bf[2][4];
#pragma unroll
            for (int mt = 0; mt < 4; mt++)
                ldsm_x4(af[mt], stA + (unsigned)(a_off + mt * 16 * SSTR + kk) * 2);
#pragma unroll
            for (int p = 0; p < 2; p++)
                ldsm_x4(bf[p], stB + (unsigned)(b_off + p * 16 * SSTR + kk) * 2);
#pragma unroll
            for (int mt = 0; mt < 4; mt++)
#pragma unroll
                for (int nt = 0; nt < 4; nt++)
                    mma_f16(acc[mt][nt], af[mt], &bf[nt >> 1][(nt & 1) * 2]);
        }

        fill  = stage;
        stage = (stage == 2) ? 0 : stage + 1;

        if (++kc == KT) {
            kc = 0;
            int bn = bn_base + sub * 128;
#pragma unroll
            for (int mt = 0; mt < 4; mt++) {
#pragma unroll
                for (int nt = 0; nt < 4; nt++) {
#pragma unroll
                    for (int h2 = 0; h2 < 2; h2++) {
                        int m = bm + wm + mt * 16 + g + (h2 ? 8 : 0);
                        int n = bn + wn + nt * 8 + t * 2;
                        float v0 = acc[mt][nt][h2 * 2 + 0] + bias[n];
                        float v1 = acc[mt][nt][h2 * 2 + 1] + bias[n + 1];
                        if (MODE == 0) {
                            int part   = n >> 10;
                            int within = n & 1023;
                            int h = within >> 6;
                            int d = within & 63;
                            int b = m >> 11;
                            int l = m & 2047;
                            size_t dst = ((size_t)(b * NHEADS + h) * SEQ + l) * HD + d;
                            __half* base = (part == 0) ? g_Q : (part == 1) ? g_K : g_V;
                            *(__half2*)(base + dst) = __floats2half2_rn(v0, v1);
                        } else {
                            float2 fv = make_float2(v0, v1);
                            *(float2*)(&Cout[(size_t)m * N + n]) = fv;
                        }
                        acc[mt][nt][h2 * 2 + 0] = 0.f;
                        acc[mt][nt][h2 * 2 + 1] = 0.f;
                    }
                }
            }
            sub++;
        }
    }
}

// ---------------------------------------------------------------------------
// Sliding-window attention: fp16 mma + ldmatrix, 2-stage cp.async K/V pipeline
// (55 KB smem -> 4 CTAs/SM), base-2 softmax (log2e folded into Q scale).
// Q-tile 64, 128 threads (4 warps x 16 query rows).
// ---------------------------------------------------------------------------
#define AST 72
#define ATT_STG_HALVES (2 * 64 * AST)          // K + V per stage
#define ATT_STG_BYTES  (ATT_STG_HALVES * 2)
#define ATT_NSTG 2

__global__ __launch_bounds__(128)
void attn_mma()
{
    extern __shared__ __half smh[];
    __half* Qs     = smh;                                 // 64 x AST
    __half* KVbase = smh + 64 * AST;                      // 2 stages of (K|V)
    __half* Ps     = KVbase + ATT_NSTG * ATT_STG_HALVES;  // 64 x AST

    int tid  = threadIdx.x;
    int lane = tid & 31;
    int wid  = tid >> 5;
    int g = lane >> 2;
    int t = lane & 3;
    int lr = lane & 7;

    int bh = blockIdx.y;
    int i0 = blockIdx.x * 64;

    const __half* Qg = g_Q + (size_t)bh * SEQ * HD;
    const __half* Kg = g_K + (size_t)bh * SEQ * HD;
    const __half* Vg = g_V + (size_t)bh * SEQ * HD;

    int rbase = wid * 16;
    int a_off = (rbase + lr + (((lane >> 3) & 1) ? 8 : 0)) * AST + ((lane >> 4) ? 8 : 0);
    int b_off = (lr + ((lane >> 4) ? 8 : 0)) * AST + (((lane >> 3) & 1) ? 8 : 0);
    int vb_off = (lr + (((lane >> 3) & 1) ? 8 : 0)) * AST + ((lane >> 4) ? 8 : 0);

    unsigned shQ  = (unsigned)__cvta_generic_to_shared(Qs);
    unsigned shKV = (unsigned)__cvta_generic_to_shared(KVbase);
    unsigned shP  = (unsigned)__cvta_generic_to_shared(Ps);

    int kv_lo = i0 - (WIN - 1);
    if (kv_lo < 0) kv_lo = 0;
    int cs0 = (kv_lo / 64) * 64;
    int n_chunks = (i0 - cs0) / 64 + 1;

    auto issueKV = [&](int s, int cs) {
        __half* dK = KVbase + s * ATT_STG_HALVES;
        __half* dV = dK + 64 * AST;
#pragma unroll
        for (int r = 0; r < 4; r++) {
            int id  = tid + r * 128;
            int row = id >> 3;
            int c   = id & 7;
            const __half* gk = Kg + (size_t)(cs + row) * HD + c * 8;
            const __half* gv = Vg + (size_t)(cs + row) * HD + c * 8;
            unsigned sk = (unsigned)__cvta_generic_to_shared(dK + row * AST + c * 8);
            unsigned sv = (unsigned)__cvta_generic_to_shared(dV + row * AST + c * 8);
            asm volatile("cp.async.cg.shared.global [%0], [%1], 16;\n" :: "r"(sk), "l"(gk));
            asm volatile("cp.async.cg.shared.global [%0], [%1], 16;\n" :: "r"(sv), "l"(gv));
        }
        asm volatile("cp.async.commit_group;\n");
    };

    issueKV(0, cs0);
    if (n_chunks > 1) issueKV(1, cs0 + 64);

    // Q staging (overlaps in-flight cp.async). Scale = 0.125 * log2(e), applied
    // in fp32 -> base-2 softmax downstream (exp2f instead of __expf).
    {
        const float QS = 0.125f * 1.44269504f;
        int q = tid >> 1, half_sel = tid & 1;
#pragma unroll
        for (int v = 0; v < 4; v++) {
            int c8 = half_sel * 32 + v * 8;
            uint2 raw = *(const uint2*)(Qg + (size_t)(i0 + q) * HD + c8);
            uint2 raw2 = *(const uint2*)(Qg + (size_t)(i0 + q) * HD + c8 + 4);
            float2 f0 = __half22float2(*(__half2*)&raw.x);
            float2 f1 = __half22float2(*(__half2*)&raw.y);
            float2 f2 = __half22float2(*(__half2*)&raw2.x);
            float2 f3 = __half22float2(*(__half2*)&raw2.y);
            __half* dst = Qs + q * AST + c8;
            *(__half2*)(dst)     = __floats2half2_rn(f0.x * QS, f0.y * QS);
            *(__half2*)(dst + 2) = __floats2half2_rn(f1.x * QS, f1.y * QS);
            *(__half2*)(dst + 4) = __floats2half2_rn(f2.x * QS, f2.y * QS);
            *(__half2*)(dst + 6) = __floats2half2_rn(f3.x * QS, f3.y * QS);
        }
    }

    int iq0 = i0 + rbase + g;
    int iq1 = iq0 + 8;

    float m0 = -1e30f, m1 = -1e30f, l0 = 0.f, l1 = 0.f;
    float oacc[8][4];
#pragma unroll
    for (int nt = 0; nt < 8; nt++)
#pragma unroll
        for (int i = 0; i < 4; i++) oacc[nt][i] = 0.f;

    for (int ci = 0; ci < n_chunks; ci++) {
        int cs = cs0 + ci * 64;
        if (ci + 1 < n_chunks) asm volatile("cp.async.wait_group 1;\n" ::: "memory");
        else                   asm volatile("cp.async.wait_group 0;\n" ::: "memory");
        __syncthreads();

        unsigned shK_st = shKV + (ci & 1) * ATT_STG_BYTES;
        unsigned shV_st = shK_st + 64 * AST * 2;

        // S = Q*K^T (base-2 scaled)
        float sacc[8][4];
#pragma unroll
        for (int nt = 0; nt < 8; nt++)
#pragma unroll
            for (int i = 0; i < 4; i++) sacc[nt][i] = 0.f;

#pragma unroll
        for (int kk = 0; kk < 4; kk++) {
            int c = kk * 16;
            unsigned af[4], bf[4][4];
            ldsm_x4(af, shQ + (unsigned)(a_off + c) * 2);
#pragma unroll
            for (int p = 0; p < 4; p++)
                ldsm_x4(bf[p], shK_st + (unsigned)(b_off + p * 16 * AST + c) * 2);
#pragma unroll
            for (int nt = 0; nt < 8; nt++)
                mma_f16(sacc[nt], af, &bf[nt >> 1][(nt & 1) * 2]);
        }

        // Mask + online softmax (base 2)
        float rmax0 = -1e30f, rmax1 = -1e30f;
#pragma unroll
        for (int nt = 0; nt < 8; nt++) {
#pragma unroll
            for (int e = 0; e < 2; e++) {
                int j = cs + nt * 8 + 2 * t + e;
                if (!((j <= iq0) && (j > iq0 - WIN))) sacc[nt][e] = -1e30f;
                if (!((j <= iq1) && (j > iq1 - WIN))) sacc[nt][2 + e] = -1e30f;
                rmax0 = fmaxf(rmax0, sacc[nt][e]);
                rmax1 = fmaxf(rmax1, sacc[nt][2 + e]);
            }
        }
#pragma unroll
        for (int msk = 1; msk < 4; msk <<= 1) {
            rmax0 = fmaxf(rmax0, __shfl_xor_sync(0xffffffffu, rmax0, msk));
            rmax1 = fmaxf(rmax1, __shfl_xor_sync(0xffffffffu, rmax1, msk));
        }

        float mn0 = fmaxf(m0, rmax0);
        float mn1 = fmaxf(m1, rmax1);
        float cor0 = exp2f(m0 - mn0);
        float cor1 = exp2f(m1 - mn1);
        m0 = mn0; m1 = mn1;

        float rs0 = 0.f, rs1 = 0.f;
#pragma unroll
        for (int nt = 0; nt < 8; nt++) {
            float p0 = exp2f(sacc[nt][0] - mn0);
            float p1 = exp2f(sacc[nt][1] - mn0);
            float p2 = exp2f(sacc[nt][2] - mn1);
            float p3 = exp2f(sacc[nt][3] - mn1);
            rs0 += p0 + p1;
            rs1 += p2 + p3;
            int col = nt * 8 + 2 * t;
            *(__half2*)(Ps + (rbase + g) * AST + col)     = __floats2half2_rn(p0, p1);
            *(__half2*)(Ps + (rbase + g + 8) * AST + col) = __floats2half2_rn(p2, p3);
        }
#pragma unroll
        for (int msk = 1; msk < 4; msk <<= 1) {
            rs0 += __shfl_xor_sync(0xffffffffu, rs0, msk);
            rs1 += __shfl_xor_sync(0xffffffffu, rs1, msk);
        }
        l0 = l0 * cor0 + rs0;
        l1 = l1 * cor1 + rs1;
#pragma unroll
        for (int nt = 0; nt < 8; nt++) {
            oacc[nt][0] *= cor0; oacc[nt][1] *= cor0;
            oacc[nt][2] *= cor1; oacc[nt][3] *= cor1;
        }
        __syncwarp();

        // O += P * V
#pragma unroll
        for (int kk = 0; kk < 4; kk++) {
            int c = kk * 16;
            unsigned af[4], bf[4][4];
            ldsm_x4(af, shP + (unsigned)(a_off + c) * 2);
#pragma unroll
            for (int p = 0; p < 4; p++)
                ldsm_x4_trans(bf[p], shV_st + (unsigned)(vb_off + c * AST + p * 16) * 2);
#pragma unroll
            for (int nt = 0; nt < 8; nt++)
                mma_f16(oacc[nt], af, &bf[nt >> 1][(nt & 1) * 2]);
        }

        // Write-after-read protection: all warps done with stage (ci&1) before
        // it is refilled for chunk ci+2.
        __syncthreads();
        if (ci + 2 < n_chunks) issueKV(ci & 1, cs + 128);
    }

    // Normalize + write fp16 O
    float inv0 = 1.f / l0;
    float inv1 = 1.f / l1;
    int b = bh / NHEADS;
    int h = bh % NHEADS;
    __half* O0 = g_O + (size_t)(b * SEQ + iq0) * D_MODEL + h * HD;
    __half* O1 = g_O + (size_t)(b * SEQ + iq1) * D_MODEL + h * HD;
#pragma unroll
    for (int nt = 0; nt < 8; nt++) {
        int d = nt * 8 + 2 * t;
        *(__half2*)(O0 + d) = __floats2half2_rn(oacc[nt][0] * inv0, oacc[nt][1] * inv0);
        *(__half2*)(O1 + d) = __floats2half2_rn(oacc[nt][2] * inv1, oacc[nt][3] * inv1);
    }
}

// ---------------------------------------------------------------------------
extern "C" void kernel_launch(void* const* d_in, const int* in_sizes, int n_in,
                              void* d_out, int out_size)
{
    const float* x  = (const float*)d_in[0];
    const float* w1 = (const float*)d_in[1];
    const float* b1 = (const float*)d_in[2];
    const float* w2 = (const float*)d_in[3];
    const float* b2 = (const float*)d_in[4];
    float* out = (float*)d_out;

    const int M = BATCH * SEQ;

    __half *cx, *cw1, *cw2;
    cudaGetSymbolAddress((void**)&cx,  c_x);
    cudaGetSymbolAddress((void**)&cw1, c_w1);
    cudaGetSymbolAddress((void**)&cw2, c_w2);

    // 0) fused fp32 -> fp16 conversion (single launch)
    {
        int n4x  = M * D_MODEL / 4;
        int n4w1 = 3 * D_MODEL * D_MODEL / 4;
        int n4w2 = D_MODEL * D_MODEL / 4;
        int total = n4x + n4w1 + n4w2;
        cvt_all<<<(total + 255) / 256, 256>>>((const float4*)x, (uint2*)cx, n4x,
                                              (const float4*)w1, (uint2*)cw1, n4w1,
                                              (const float4*)w2, (uint2*)cw2, n4w2);
    }

    const int gemm_smem = 2 * NSTG * STG_BYTES;   // 110592 B

    // 1) QKV projection: persistent, 256 CTAs x 3 tiles
    {
        cudaFuncSetAttribute(gemm_f16<0, 3>,
                             cudaFuncAttributeMaxDynamicSharedMemorySize, gemm_smem);
        gemm_f16<0, 3><<<256, 256, gemm_smem>>>(cx, cw1, b1, nullptr,
                                                M, 3 * D_MODEL, D_MODEL);
    }

    // 2) Sliding-window attention (2-stage pipeline, base-2 softmax)
    {
        int smem = (64 * AST + ATT_NSTG * ATT_STG_HALVES + 64 * AST) * (int)sizeof(__half); // 55296
        cudaFuncSetAttribute(attn_mma,
                             cudaFuncAttributeMaxDynamicSharedMemorySize, smem);
        dim3 grid(SEQ / 64, BATCH * NHEADS);
        attn_mma<<<grid, 128, smem>>>();
    }

    // 3) Output projection: 256 CTAs x 1 tile (single wave)
    {
        cudaFuncSetAttribute(gemm_f16<1, 1>,
                             cudaFuncAttributeMaxDynamicSharedMemorySize, gemm_smem);
        gemm_f16<1, 1><<<256, 256, gemm_smem>>>(nullptr, cw2, b2, out,
                                                M, D_MODEL, D_MODEL);
    }
}

// round 16
// speedup vs baseline: 1.2044x; 1.0013x over previous
#include <cuda_runtime.h>
#include <cuda_fp16.h>
#include <math.h>
#include <stdint.h>

#define D_MODEL 1024
#define NHEADS  16
#define HD      64
#define SEQ     2048
#define BATCH   2
#define WIN     256

// Scratch (allocation-free: __device__ globals). All fp16.
// g_Q holds PRE-SCALED queries: q * 0.125 * log2(e)  (base-2 softmax).
__device__ __half g_Q[BATCH * NHEADS * SEQ * HD];   // [b][h][l][d]
__device__ __half g_K[BATCH * NHEADS * SEQ * HD];
__device__ __half g_V[BATCH * NHEADS * SEQ * HD];
__device__ __half g_O[BATCH * SEQ * D_MODEL];       // [b][l][h*64+d]
__device__ __half c_x [BATCH * SEQ * D_MODEL];
__device__ __half c_w1[3 * D_MODEL * D_MODEL];
__device__ __half c_w2[D_MODEL * D_MODEL];

#define QSCALE 0.1803368801111f   // 0.125 * log2(e)

__device__ __forceinline__ void mma_f16(float c[4], const unsigned a[4], const unsigned b[2]) {
    asm volatile(
        "mma.sync.aligned.m16n8k16.row.col.f32.f16.f16.f32 "
        "{%0,%1,%2,%3}, {%4,%5,%6,%7}, {%8,%9}, {%0,%1,%2,%3};\n"
        : "+f"(c[0]), "+f"(c[1]), "+f"(c[2]), "+f"(c[3])
        : "r"(a[0]), "r"(a[1]), "r"(a[2]), "r"(a[3]),
          "r"(b[0]), "r"(b[1]));
}

__device__ __forceinline__ void ldsm_x4(unsigned a[4], unsigned saddr) {
    asm volatile("ldmatrix.sync.aligned.m8n8.x4.shared.b16 {%0,%1,%2,%3}, [%4];"
        : "=r"(a[0]), "=r"(a[1]), "=r"(a[2]), "=r"(a[3]) : "r"(saddr));
}

__device__ __forceinline__ void ldsm_x4_trans(unsigned a[4], unsigned saddr) {
    asm volatile("ldmatrix.sync.aligned.m8n8.x4.trans.shared.b16 {%0,%1,%2,%3}, [%4];"
        : "=r"(a[0]), "=r"(a[1]), "=r"(a[2]), "=r"(a[3]) : "r"(saddr));
}

// ---------------------------------------------------------------------------
// Fused fp32 -> fp16 bulk converter for x, w1, w2 (one launch)
// ---------------------------------------------------------------------------
__global__ void cvt_all(const float4* __restrict__ x,  uint2* __restrict__ cx,  int n4x,
                        const float4* __restrict__ w1, uint2* __restrict__ cw1, int n4w1,
                        const float4* __restrict__ w2, uint2* __restrict__ cw2, int n4w2)
{
    int i = blockIdx.x * blockDim.x + threadIdx.x;
    const float4* src;
    uint2* dst;
    int idx;
    if (i < n4x)                   { src = x;  dst = cx;  idx = i; }
    else if (i < n4x + n4w1)       { src = w1; dst = cw1; idx = i - n4x; }
    else if (i < n4x + n4w1 + n4w2){ src = w2; dst = cw2; idx = i - n4x - n4w1; }
    else return;
    float4 v = src[idx];
    __half2 h01 = __floats2half2_rn(v.x, v.y);
    __half2 h23 = __floats2half2_rn(v.z, v.w);
    uint2 u;
    u.x = *(unsigned*)&h01;
    u.y = *(unsigned*)&h23;
    dst[idx] = u;
}

// ---------------------------------------------------------------------------
// Persistent FP16 NT GEMM (fp32 accum), BK=64, 3-stage cp.async pipeline.
// MODE 0: Q part written pre-scaled by QSCALE.
// ---------------------------------------------------------------------------
#define SSTR 72
#define BK   64
#define STG_HALVES (128 * SSTR)
#define STG_BYTES  (STG_HALVES * 2)
#define NSTG 3

template <int MODE, int NSUB>
__global__ __launch_bounds__(256, 2)
void gemm_f16(const __half* __restrict__ A, const __half* __restrict__ W,
              const float* __restrict__ bias, float* __restrict__ Cout,
              int M, int N, int K)
{
    extern __shared__ __half sh[];
    __half* AsBase = sh;
    __half* BsBase = sh + NSTG * STG_HALVES;

    const __half* Ap = (MODE == 1) ? (const __half*)g_O : A;

    int tid  = threadIdx.x;
    int lane = tid & 31;
    int wid  = tid >> 5;
    int wm = (wid >> 2) * 64;
    int wn = (wid & 3) * 32;
    int bx = blockIdx.x;
    int bm      = (bx >> 3) * 128;
    int bn_base = (bx & 7) * (NSUB * 128);
    int g = lane >> 2;
    int t = lane & 3;
    int lr = lane & 7;

    int a_off = (wm + lr + (((lane >> 3) & 1) ? 8 : 0)) * SSTR + ((lane >> 4) ? 8 : 0);
    int b_off = (wn + lr + ((lane >> 4) ? 8 : 0)) * SSTR + (((lane >> 3) & 1) ? 8 : 0);

    unsigned shA = (unsigned)__cvta_generic_to_shared(AsBase);
    unsigned shB = (unsigned)__cvta_generic_to_shared(BsBase);

    float acc[4][4][4];
#pragma unroll
    for (int mt = 0; mt < 4; mt++)
#pragma unroll
        for (int nt = 0; nt < 4; nt++)
#pragma unroll
            for (int i = 0; i < 4; i++) acc[mt][nt][i] = 0.f;

    const int KT = K / BK;
    const int TOTAL = KT * NSUB;

    auto issue = [&](int s, int tt) {
        int sub = tt / KT;
        int k0  = (tt - sub * KT) * BK;
        int bn  = bn_base + sub * 128;
        __half* dA = AsBase + s * STG_HALVES;
        __half* dB = BsBase + s * STG_HALVES;
#pragma unroll
        for (int r = 0; r < 4; r++) {
            int id  = tid + r * 256;
            int row = id >> 3;
            int c   = id & 7;
            const __half* ga = Ap + (size_t)(bm + row) * K + k0 + c * 8;
            const __half* gb = W  + (size_t)(bn + row) * K + k0 + c * 8;
            unsigned sa = (unsigned)__cvta_generic_to_shared(dA + row * SSTR + c * 8);
            unsigned sb = (unsigned)__cvta_generic_to_shared(dB + row * SSTR + c * 8);
            asm volatile("cp.async.cg.shared.global [%0], [%1], 16;\n" :: "r"(sa), "l"(ga));
            asm volatile("cp.async.cg.shared.global [%0], [%1], 16;\n" :: "r"(sb), "l"(gb));
        }
        asm volatile("cp.async.commit_group;\n");
    };

    issue(0, 0);
    issue(1, 1);

    int stage = 0, fill = 2;
    int kc = 0, sub = 0;

    for (int tt = 0; tt < TOTAL; tt++) {
        if (tt + 1 < TOTAL) asm volatile("cp.async.wait_group 1;\n" ::: "memory");
        else                asm volatile("cp.async.wait_group 0;\n" ::: "memory");
        __syncthreads();

        if (tt + 2 < TOTAL) issue(fill, tt + 2);

        unsigned stA = shA + stage * STG_BYTES;
        unsigned stB = shB + stage * STG_BYTES;

#pragma unroll
        for (int ks = 0; ks < 4; ks++) {
            int kk = ks * 16;
            unsigned af[4][4], bf[2][4];
#pragma unroll
            for (int mt = 0; mt < 4; mt++)
                ldsm_x4(af[mt], stA + (unsigned)(a_off + mt * 16 * SSTR + kk) * 2);
#pragma unroll
            for (int p = 0; p < 2; p++)
                ldsm_x4(bf[p], stB + (unsigned)(b_off + p * 16 * SSTR + kk) * 2);
#pragma unroll
            for (int mt = 0; mt < 4; mt++)
#pragma unroll
                for (int nt = 0; nt < 4; nt++)
                    mma_f16(acc[mt][nt], af[mt], &bf[nt >> 1][(nt & 1) * 2]);
        }

        fill  = stage;
        stage = (stage == 2) ? 0 : stage + 1;

        if (++kc == KT) {
            kc = 0;
            int bn = bn_base + sub * 128;
#pragma unroll
            for (int mt = 0; mt < 4; mt++) {
#pragma unroll
                for (int nt = 0; nt < 4; nt++) {
#pragma unroll
                    for (int h2 = 0; h2 < 2; h2++) {
                        int m = bm + wm + mt * 16 + g + (h2 ? 8 : 0);
                        int n = bn + wn + nt * 8 + t * 2;
                        float v0 = acc[mt][nt][h2 * 2 + 0] + bias[n];
                        float v1 = acc[mt][nt][h2 * 2 + 1] + bias[n + 1];
                        if (MODE == 0) {
                            int part   = n >> 10;
                            int within = n & 1023;
                            int h = within >> 6;
                            int d = within & 63;
                            int b = m >> 11;
                            int l = m & 2047;
                            size_t dst = ((size_t)(b * NHEADS + h) * SEQ + l) * HD + d;
                            __half* base = (part == 0) ? g_Q : (part == 1) ? g_K : g_V;
                            float s = (part == 0) ? QSCALE : 1.0f;   // pre-scale Q
                            *(__half2*)(base + dst) = __floats2half2_rn(v0 * s, v1 * s);
                        } else {
                            float2 fv = make_float2(v0, v1);
                            *(float2*)(&Cout[(size_t)m * N + n]) = fv;
                        }
                        acc[mt][nt][h2 * 2 + 0] = 0.f;
                        acc[mt][nt][h2 * 2 + 1] = 0.f;
                    }
                }
            }
            sub++;
        }
    }
}

// ---------------------------------------------------------------------------
// Sliding-window attention: fp16 mma + ldmatrix, 2-stage cp.async K/V pipeline,
// base-2 softmax (Q arrives pre-scaled), Q staged via cp.async in group 0.
// Q-tile 64, 128 threads (4 warps x 16 query rows).
// ---------------------------------------------------------------------------
#define AST 72
#define ATT_STG_HALVES (2 * 64 * AST)          // K + V per stage
#define ATT_STG_BYTES  (ATT_STG_HALVES * 2)
#define ATT_NSTG 2

__global__ __launch_bounds__(128)
void attn_mma()
{
    extern __shared__ __half smh[];
    __half* Qs     = smh;                                 // 64 x AST
    __half* KVbase = smh + 64 * AST;                      // 2 stages of (K|V)
    __half* Ps     = KVbase + ATT_NSTG * ATT_STG_HALVES;  // 64 x AST

    int tid  = threadIdx.x;
    int lane = tid & 31;
    int wid  = tid >> 5;
    int g = lane >> 2;
    int t = lane & 3;
    int lr = lane & 7;

    int bh = blockIdx.y;
    int i0 = blockIdx.x * 64;

    const __half* Qg = g_Q + (size_t)bh * SEQ * HD;
    const __half* Kg = g_K + (size_t)bh * SEQ * HD;
    const __half* Vg = g_V + (size_t)bh * SEQ * HD;

    int rbase = wid * 16;
    int a_off = (rbase + lr + (((lane >> 3) & 1) ? 8 : 0)) * AST + ((lane >> 4) ? 8 : 0);
    int b_off = (lr + ((lane >> 4) ? 8 : 0)) * AST + (((lane >> 3) & 1) ? 8 : 0);
    int vb_off = (lr + (((lane >> 3) & 1) ? 8 : 0)) * AST + ((lane >> 4) ? 8 : 0);

    unsigned shQ  = (unsigned)__cvta_generic_to_shared(Qs);
    unsigned shKV = (unsigned)__cvta_generic_to_shared(KVbase);
    unsigned shP  = (unsigned)__cvta_generic_to_shared(Ps);

    int kv_lo = i0 - (WIN - 1);
    if (kv_lo < 0) kv_lo = 0;
    int cs0 = (kv_lo / 64) * 64;
    int n_chunks = (i0 - cs0) / 64 + 1;

    // K/V chunk loads into stage s (NO commit — caller commits the group)
    auto issueKV = [&](int s, int cs) {
        __half* dK = KVbase + s * ATT_STG_HALVES;
        __half* dV = dK + 64 * AST;
#pragma unroll
        for (int r = 0; r < 4; r++) {
            int id  = tid + r * 128;
            int row = id >> 3;
            int c   = id & 7;
            const __half* gk = Kg + (size_t)(cs + row) * HD + c * 8;
            const __half* gv = Vg + (size_t)(cs + row) * HD + c * 8;
            unsigned sk = (unsigned)__cvta_generic_to_shared(dK + row * AST + c * 8);
            unsigned sv = (unsigned)__cvta_generic_to_shared(dV + row * AST + c * 8);
            asm volatile("cp.async.cg.shared.global [%0], [%1], 16;\n" :: "r"(sk), "l"(gk));
            asm volatile("cp.async.cg.shared.global [%0], [%1], 16;\n" :: "r"(sv), "l"(gv));
        }
    };

    // Group 0: Q tile (pre-scaled in gmem -> raw async copy) + KV chunk 0
    {
#pragma unroll
        for (int r = 0; r < 4; r++) {
            int id  = tid + r * 128;
            int row = id >> 3;
            int c   = id & 7;
            const __half* gq = Qg + (size_t)(i0 + row) * HD + c * 8;
            unsigned sq = (unsigned)__cvta_generic_to_shared(Qs + row * AST + c * 8);
            asm volatile("cp.async.cg.shared.global [%0], [%1], 16;\n" :: "r"(sq), "l"(gq));
        }
        issueKV(0, cs0);
        asm volatile("cp.async.commit_group;\n");
    }
    if (n_chunks > 1) {
        issueKV(1, cs0 + 64);
        asm volatile("cp.async.commit_group;\n");
    }

    int iq0 = i0 + rbase + g;
    int iq1 = iq0 + 8;

    float m0 = -1e30f, m1 = -1e30f, l0 = 0.f, l1 = 0.f;
    float oacc[8][4];
#pragma unroll
    for (int nt = 0; nt < 8; nt++)
#pragma unroll
        for (int i = 0; i < 4; i++) oacc[nt][i] = 0.f;

    for (int ci = 0; ci < n_chunks; ci++) {
        int cs = cs0 + ci * 64;
        if (ci + 1 < n_chunks) asm volatile("cp.async.wait_group 1;\n" ::: "memory");
        else                   asm volatile("cp.async.wait_group 0;\n" ::: "memory");
        __syncthreads();

        unsigned shK_st = shKV + (ci & 1) * ATT_STG_BYTES;
        unsigned shV_st = shK_st + 64 * AST * 2;

        // S = Q*K^T (Q pre-scaled; scores in base-2 log domain)
        float sacc[8][4];
#pragma unroll
        for (int nt = 0; nt < 8; nt++)
#pragma unroll
            for (int i = 0; i < 4; i++) sacc[nt][i] = 0.f;

#pragma unroll
        for (int kk = 0; kk < 4; kk++) {
            int c = kk * 16;
            unsigned af[4], bf[4][4];
            ldsm_x4(af, shQ + (unsigned)(a_off + c) * 2);
#pragma unroll
            for (int p = 0; p < 4; p++)
                ldsm_x4(bf[p], shK_st + (unsigned)(b_off + p * 16 * AST + c) * 2);
#pragma unroll
            for (int nt = 0; nt < 8; nt++)
                mma_f16(sacc[nt], af, &bf[nt >> 1][(nt & 1) * 2]);
        }

        // Mask + online softmax (base 2)
        float rmax0 = -1e30f, rmax1 = -1e30f;
#pragma unroll
        for (int nt = 0; nt < 8; nt++) {
#pragma unroll
            for (int e = 0; e < 2; e++) {
                int j = cs + nt * 8 + 2 * t + e;
                if (!((j <= iq0) && (j > iq0 - WIN))) sacc[nt][e] = -1e30f;
                if (!((j <= iq1) && (j > iq1 - WIN))) sacc[nt][2 + e] = -1e30f;
                rmax0 = fmaxf(rmax0, sacc[nt][e]);
                rmax1 = fmaxf(rmax1, sacc[nt][2 + e]);
            }
        }
#pragma unroll
        for (int msk = 1; msk < 4; msk <<= 1) {
            rmax0 = fmaxf(rmax0, __shfl_xor_sync(0xffffffffu, rmax0, msk));
            rmax1 = fmaxf(rmax1, __shfl_xor_sync(0xffffffffu, rmax1, msk));
        }

        float mn0 = fmaxf(m0, rmax0);
        float mn1 = fmaxf(m1, rmax1);
        float cor0 = exp2f(m0 - mn0);
        float cor1 = exp2f(m1 - mn1);
        m0 = mn0; m1 = mn1;

        float rs0 = 0.f, rs1 = 0.f;
#pragma unroll
        for (int nt = 0; nt < 8; nt++) {
            float p0 = exp2f(sacc[nt][0] - mn0);
            float p1 = exp2f(sacc[nt][1] - mn0);
            float p2 = exp2f(sacc[nt][2] - mn1);
            float p3 = exp2f(sacc[nt][3] - mn1);
            rs0 += p0 + p1;
            rs1 += p2 + p3;
            int col = nt * 8 + 2 * t;
            *(__half2*)(Ps + (rbase + g) * AST + col)     = __floats2half2_rn(p0, p1);
            *(__half2*)(Ps + (rbase + g + 8) * AST + col) = __floats2half2_rn(p2, p3);
        }
#pragma unroll
        for (int msk = 1; msk < 4; msk <<= 1) {
            rs0 += __shfl_xor_sync(0xffffffffu, rs0, msk);
            rs1 += __shfl_xor_sync(0xffffffffu, rs1, msk);
        }
        l0 = l0 * cor0 + rs0;
        l1 = l1 * cor1 + rs1;
#pragma unroll
        for (int nt = 0; nt < 8; nt++) {
            oacc[nt][0] *= cor0; oacc[nt][1] *= cor0;
            oacc[nt][2] *= cor1; oacc[nt][3] *= cor1;
        }
        __syncwarp();

        // O += P * V
#pragma unroll
        for (int kk = 0; kk < 4; kk++) {
            int c = kk * 16;
            unsigned af[4], bf[4][4];
            ldsm_x4(af, shP + (unsigned)(a_off + c) * 2);
#pragma unroll
            for (int p = 0; p < 4; p++)
                ldsm_x4_trans(bf[p], shV_st + (unsigned)(vb_off + c * AST + p * 16) * 2);
#pragma unroll
            for (int nt = 0; nt < 8; nt++)
                mma_f16(oacc[nt], af, &bf[nt >> 1][(nt & 1) * 2]);
        }

        // Write-after-read protection before refilling stage (ci&1)
        __syncthreads();
        if (ci + 2 < n_chunks) {
            issueKV(ci & 1, cs + 128);
            asm volatile("cp.async.commit_group;\n");
        }
    }

    // Normalize + write fp16 O
    float inv0 = 1.f / l0;
    float inv1 = 1.f / l1;
    int b = bh / NHEADS;
    int h = bh % NHEADS;
    __half* O0 = g_O + (size_t)(b * SEQ + iq0) * D_MODEL + h * HD;
    __half* O1 = g_O + (size_t)(b * SEQ + iq1) * D_MODEL + h * HD;
#pragma unroll
    for (int nt = 0; nt < 8; nt++) {
        int d = nt * 8 + 2 * t;
        *(__half2*)(O0 + d) = __floats2half2_rn(oacc[nt][0] * inv0, oacc[nt][1] * inv0);
        *(__half2*)(O1 + d) = __floats2half2_rn(oacc[nt][2] * inv1, oacc[nt][3] * inv1);
    }
}

// ---------------------------------------------------------------------------
extern "C" void kernel_launch(void* const* d_in, const int* in_sizes, int n_in,
                              void* d_out, int out_size)
{
    const float* x  = (const float*)d_in[0];
    const float* w1 = (const float*)d_in[1];
    const float* b1 = (const float*)d_in[2];
    const float* w2 = (const float*)d_in[3];
    const float* b2 = (const float*)d_in[4];
    float* out = (float*)d_out;

    const int M = BATCH * SEQ;

    __half *cx, *cw1, *cw2;
    cudaGetSymbolAddress((void**)&cx,  c_x);
    cudaGetSymbolAddress((void**)&cw1, c_w1);
    cudaGetSymbolAddress((void**)&cw2, c_w2);

    // 0) fused fp32 -> fp16 conversion (single launch)
    {
        int n4x  = M * D_MODEL / 4;
        int n4w1 = 3 * D_MODEL * D_MODEL / 4;
        int n4w2 = D_MODEL * D_MODEL / 4;
        int total = n4x + n4w1 + n4w2;
        cvt_all<<<(total + 255) / 256, 256>>>((const float4*)x, (uint2*)cx, n4x,
                                              (const float4*)w1, (uint2*)cw1, n4w1,
                                              (const float4*)w2, (uint2*)cw2, n4w2);
    }

    const int gemm_smem = 2 * NSTG * STG_BYTES;   // 110592 B

    // 1) QKV projection: persistent, 256 CTAs x 3 tiles (Q pre-scaled)
    {
        cudaFuncSetAttribute(gemm_f16<0, 3>,
                             cudaFuncAttributeMaxDynamicSharedMemorySize, gemm_smem);
        gemm_f16<0, 3><<<256, 256, gemm_smem>>>(cx, cw1, b1, nullptr,
                                                M, 3 * D_MODEL, D_MODEL);
    }

    // 2) Sliding-window attention (2-stage pipeline, async Q, base-2 softmax)
    {
        int smem = (64 * AST + ATT_NSTG * ATT_STG_HALVES + 64 * AST) * (int)sizeof(__half); // 55296
        cudaFuncSetAttribute(attn_mma,
                             cudaFuncAttributeMaxDynamicSharedMemorySize, smem);
        dim3 grid(SEQ / 64, BATCH * NHEADS);
        attn_mma<<<grid, 128, smem>>>();
    }

    // 3) Output projection: 256 CTAs x 1 tile (single wave)
    {
        cudaFuncSetAttribute(gemm_f16<1, 1>,
                             cudaFuncAttributeMaxDynamicSharedMemorySize, gemm_smem);
        gemm_f16<1, 1><<<256, 256, gemm_smem>>>(nullptr, cw2, b2, out,
                                                M, D_MODEL, D_MODEL);
    }
}

// round 17
// speedup vs baseline: 1.2057x; 1.0012x over previous
#include <cuda_runtime.h>
#include <cuda_fp16.h>
#include <math.h>
#include <stdint.h>

#define D_MODEL 1024
#define NHEADS  16
#define HD      64
#define SEQ     2048
#define BATCH   2
#define WIN     256

// Scratch (allocation-free: __device__ globals). All fp16.
// g_Q holds PRE-SCALED queries: q * 0.125 * log2(e)  (base-2 softmax).
__device__ __half g_Q[BATCH * NHEADS * SEQ * HD];   // [b][h][l][d]
__device__ __half g_K[BATCH * NHEADS * SEQ * HD];
__device__ __half g_V[BATCH * NHEADS * SEQ * HD];
__device__ __half g_O[BATCH * SEQ * D_MODEL];       // [b][l][h*64+d]
__device__ __half c_x [BATCH * SEQ * D_MODEL];
__device__ __half c_w1[3 * D_MODEL * D_MODEL];
__device__ __half c_w2[D_MODEL * D_MODEL];

#define QSCALE 0.1803368801111f   // 0.125 * log2(e)

__device__ __forceinline__ void mma_f16(float c[4], const unsigned a[4], const unsigned b[2]) {
    asm volatile(
        "mma.sync.aligned.m16n8k16.row.col.f32.f16.f16.f32 "
        "{%0,%1,%2,%3}, {%4,%5,%6,%7}, {%8,%9}, {%0,%1,%2,%3};\n"
        : "+f"(c[0]), "+f"(c[1]), "+f"(c[2]), "+f"(c[3])
        : "r"(a[0]), "r"(a[1]), "r"(a[2]), "r"(a[3]),
          "r"(b[0]), "r"(b[1]));
}

__device__ __forceinline__ void ldsm_x4(unsigned a[4], unsigned saddr) {
    asm volatile("ldmatrix.sync.aligned.m8n8.x4.shared.b16 {%0,%1,%2,%3}, [%4];"
        : "=r"(a[0]), "=r"(a[1]), "=r"(a[2]), "=r"(a[3]) : "r"(saddr));
}

__device__ __forceinline__ void ldsm_x4_trans(unsigned a[4], unsigned saddr) {
    asm volatile("ldmatrix.sync.aligned.m8n8.x4.trans.shared.b16 {%0,%1,%2,%3}, [%4];"
        : "=r"(a[0]), "=r"(a[1]), "=r"(a[2]), "=r"(a[3]) : "r"(saddr));
}

__device__ __forceinline__ float ex2(float x) {
    float r;
    asm("ex2.approx.f32 %0, %1;" : "=f"(r) : "f"(x));
    return r;
}

// ---------------------------------------------------------------------------
// Fused fp32 -> fp16 bulk converter for x, w1, w2 (one launch)
// ---------------------------------------------------------------------------
__global__ void cvt_all(const float4* __restrict__ x,  uint2* __restrict__ cx,  int n4x,
                        const float4* __restrict__ w1, uint2* __restrict__ cw1, int n4w1,
                        const float4* __restrict__ w2, uint2* __restrict__ cw2, int n4w2)
{
    int i = blockIdx.x * blockDim.x + threadIdx.x;
    const float4* src;
    uint2* dst;
    int idx;
    if (i < n4x)                   { src = x;  dst = cx;  idx = i; }
    else if (i < n4x + n4w1)       { src = w1; dst = cw1; idx = i - n4x; }
    else if (i < n4x + n4w1 + n4w2){ src = w2; dst = cw2; idx = i - n4x - n4w1; }
    else return;
    float4 v = src[idx];
    __half2 h01 = __floats2half2_rn(v.x, v.y);
    __half2 h23 = __floats2half2_rn(v.z, v.w);
    uint2 u;
    u.x = *(unsigned*)&h01;
    u.y = *(unsigned*)&h23;
    dst[idx] = u;
}

// ---------------------------------------------------------------------------
// Persistent FP16 NT GEMM (fp32 accum), BK=64, 3-stage cp.async pipeline,
// DOUBLE-BUFFERED ldmatrix fragments (LDSM of ks+1 overlaps MMAs of ks).
// MODE 0: Q part written pre-scaled by QSCALE.
// ---------------------------------------------------------------------------
#define SSTR 72
#define BK   64
#define STG_HALVES (128 * SSTR)
#define STG_BYTES  (STG_HALVES * 2)
#define NSTG 3

template <int MODE, int NSUB>
__global__ __launch_bounds__(256, 2)
void gemm_f16(const __half* __restrict__ A, const __half* __restrict__ W,
              const float* __restrict__ bias, float* __restrict__ Cout,
              int M, int N, int K)
{
    extern __shared__ __half sh[];
    __half* AsBase = sh;
    __half* BsBase = sh + NSTG * STG_HALVES;

    const __half* Ap = (MODE == 1) ? (const __half*)g_O : A;

    int tid  = threadIdx.x;
    int lane = tid & 31;
    int wid  = tid >> 5;
    int wm = (wid >> 2) * 64;
    int wn = (wid & 3) * 32;
    int bx = blockIdx.x;
    int bm      = (bx >> 3) * 128;
    int bn_base = (bx & 7) * (NSUB * 128);
    int g = lane >> 2;
    int t = lane & 3;
    int lr = lane & 7;

    int a_off = (wm + lr + (((lane >> 3) & 1) ? 8 : 0)) * SSTR + ((lane >> 4) ? 8 : 0);
    int b_off = (wn + lr + ((lane >> 4) ? 8 : 0)) * SSTR + (((lane >> 3) & 1) ? 8 : 0);

    unsigned shA = (unsigned)__cvta_generic_to_shared(AsBase);
    unsigned shB = (unsigned)__cvta_generic_to_shared(BsBase);

    float acc[4][4][4];
#pragma unroll
    for (int mt = 0; mt < 4; mt++)
#pragma unroll
        for (int nt = 0; nt < 4; nt++)
#pragma unroll
            for (int i = 0; i < 4; i++) acc[mt][nt][i] = 0.f;

    const int KT = K / BK;
    const int TOTAL = KT * NSUB;

    auto issue = [&](int s, int tt) {
        int sub = tt / KT;
        int k0  = (tt - sub * KT) * BK;
        int bn  = bn_base + sub * 128;
        __half* dA = AsBase + s * STG_HALVES;
        __half* dB = BsBase + s * STG_HALVES;
#pragma unroll
        for (int r = 0; r < 4; r++) {
            int id  = tid + r * 256;
            int row = id >> 3;
            int c   = id & 7;
            const __half* ga = Ap + (size_t)(bm + row) * K + k0 + c * 8;
            const __half* gb = W  + (size_t)(bn + row) * K + k0 + c * 8;
            unsigned sa = (unsigned)__cvta_generic_to_shared(dA + row * SSTR + c * 8);
            unsigned sb = (unsigned)__cvta_generic_to_shared(dB + row * SSTR + c * 8);
            asm volatile("cp.async.cg.shared.global [%0], [%1], 16;\n" :: "r"(sa), "l"(ga));
            asm volatile("cp.async.cg.shared.global [%0], [%1], 16;\n" :: "r"(sb), "l"(gb));
        }
        asm volatile("cp.async.commit_group;\n");
    };

    issue(0, 0);
    issue(1, 1);

    int stage = 0, fill = 2;
    int kc = 0, sub = 0;

    unsigned af[2][4][4], bf[2][2][4];

    for (int tt = 0; tt < TOTAL; tt++) {
        if (tt + 1 < TOTAL) asm volatile("cp.async.wait_group 1;\n" ::: "memory");
        else                asm volatile("cp.async.wait_group 0;\n" ::: "memory");
        __syncthreads();

        unsigned stA = shA + stage * STG_BYTES;
        unsigned stB = shB + stage * STG_BYTES;

        // Prime fragments for ks=0 BEFORE the cp.async burst
#pragma unroll
        for (int mt = 0; mt < 4; mt++)
            ldsm_x4(af[0][mt], stA + (unsigned)(a_off + mt * 16 * SSTR) * 2);
#pragma unroll
        for (int p = 0; p < 2; p++)
            ldsm_x4(bf[0][p], stB + (unsigned)(b_off + p * 16 * SSTR) * 2);

        if (tt + 2 < TOTAL) issue(fill, tt + 2);

#pragma unroll
        for (int ks = 0; ks < 4; ks++) {
            int cur = ks & 1;
            int nxt = cur ^ 1;
            if (ks < 3) {
                int kk = (ks + 1) * 16;
#pragma unroll
                for (int mt = 0; mt < 4; mt++)
                    ldsm_x4(af[nxt][mt], stA + (unsigned)(a_off + mt * 16 * SSTR + kk) * 2);
#pragma unroll
                for (int p = 0; p < 2; p++)
                    ldsm_x4(bf[nxt][p], stB + (unsigned)(b_off + p * 16 * SSTR + kk) * 2);
            }
#pragma unroll
            for (int mt = 0; mt < 4; mt++)
#pragma unroll
                for (int nt = 0; nt < 4; nt++)
                    mma_f16(acc[mt][nt], af[cur][mt], &bf[cur][nt >> 1][(nt & 1) * 2]);
        }

        fill  = stage;
        stage = (stage == 2) ? 0 : stage + 1;

        if (++kc == KT) {
            kc = 0;
            int bn = bn_base + sub * 128;
#pragma unroll
            for (int mt = 0; mt < 4; mt++) {
#pragma unroll
                for (int nt = 0; nt < 4; nt++) {
#pragma unroll
                    for (int h2 = 0; h2 < 2; h2++) {
                        int m = bm + wm + mt * 16 + g + (h2 ? 8 : 0);
                        int n = bn + wn + nt * 8 + t * 2;
                        float v0 = acc[mt][nt][h2 * 2 + 0] + bias[n];
                        float v1 = acc[mt][nt][h2 * 2 + 1] + bias[n + 1];
                        if (MODE == 0) {
                            int part   = n >> 10;
                            int within = n & 1023;
                            int h = within >> 6;
                            int d = within & 63;
                            int b = m >> 11;
                            int l = m & 2047;
                            size_t dst = ((size_t)(b * NHEADS + h) * SEQ + l) * HD + d;
                            __half* base = (part == 0) ? g_Q : (part == 1) ? g_K : g_V;
                            float s = (part == 0) ? QSCALE : 1.0f;
                            *(__half2*)(base + dst) = __floats2half2_rn(v0 * s, v1 * s);
                        } else {
                            float2 fv = make_float2(v0, v1);
                            *(float2*)(&Cout[(size_t)m * N + n]) = fv;
                        }
                        acc[mt][nt][h2 * 2 + 0] = 0.f;
                        acc[mt][nt][h2 * 2 + 1] = 0.f;
                    }
                }
            }
            sub++;
        }
    }
}

// ---------------------------------------------------------------------------
// Sliding-window attention: fp16 mma + ldmatrix, 2-stage cp.async K/V pipeline,
// base-2 softmax (Q pre-scaled; ex2.approx), async Q staging.
// Q-tile 64, 128 threads (4 warps x 16 query rows).
// ---------------------------------------------------------------------------
#define AST 72
#define ATT_STG_HALVES (2 * 64 * AST)
#define ATT_STG_BYTES  (ATT_STG_HALVES * 2)
#define ATT_NSTG 2

__global__ __launch_bounds__(128)
void attn_mma()
{
    extern __shared__ __half smh[];
    __half* Qs     = smh;
    __half* KVbase = smh + 64 * AST;
    __half* Ps     = KVbase + ATT_NSTG * ATT_STG_HALVES;

    int tid  = threadIdx.x;
    int lane = tid & 31;
    int wid  = tid >> 5;
    int g = lane >> 2;
    int t = lane & 3;
    int lr = lane & 7;

    int bh = blockIdx.y;
    int i0 = blockIdx.x * 64;

    const __half* Qg = g_Q + (size_t)bh * SEQ * HD;
    const __half* Kg = g_K + (size_t)bh * SEQ * HD;
    const __half* Vg = g_V + (size_t)bh * SEQ * HD;

    int rbase = wid * 16;
    int a_off = (rbase + lr + (((lane >> 3) & 1) ? 8 : 0)) * AST + ((lane >> 4) ? 8 : 0);
    int b_off = (lr + ((lane >> 4) ? 8 : 0)) * AST + (((lane >> 3) & 1) ? 8 : 0);
    int vb_off = (lr + (((lane >> 3) & 1) ? 8 : 0)) * AST + ((lane >> 4) ? 8 : 0);

    unsigned shQ  = (unsigned)__cvta_generic_to_shared(Qs);
    unsigned shKV = (unsigned)__cvta_generic_to_shared(KVbase);
    unsigned shP  = (unsigned)__cvta_generic_to_shared(Ps);

    int kv_lo = i0 - (WIN - 1);
    if (kv_lo < 0) kv_lo = 0;
    int cs0 = (kv_lo / 64) * 64;
    int n_chunks = (i0 - cs0) / 64 + 1;

    auto issueKV = [&](int s, int cs) {
        __half* dK = KVbase + s * ATT_STG_HALVES;
        __half* dV = dK + 64 * AST;
#pragma unroll
        for (int r = 0; r < 4; r++) {
            int id  = tid + r * 128;
            int row = id >> 3;
            int c   = id & 7;
            const __half* gk = Kg + (size_t)(cs + row) * HD + c * 8;
            const __half* gv = Vg + (size_t)(cs + row) * HD + c * 8;
            unsigned sk = (unsigned)__cvta_generic_to_shared(dK + row * AST + c * 8);
            unsigned sv = (unsigned)__cvta_generic_to_shared(dV + row * AST + c * 8);
            asm volatile("cp.async.cg.shared.global [%0], [%1], 16;\n" :: "r"(sk), "l"(gk));
            asm volatile("cp.async.cg.shared.global [%0], [%1], 16;\n" :: "r"(sv), "l"(gv));
        }
    };

    // Group 0: Q tile (raw async copy; pre-scaled in gmem) + KV chunk 0
    {
#pragma unroll
        for (int r = 0; r < 4; r++) {
            int id  = tid + r * 128;
            int row = id >> 3;
            int c   = id & 7;
            const __half* gq = Qg + (size_t)(i0 + row) * HD + c * 8;
            unsigned sq = (unsigned)__cvta_generic_to_shared(Qs + row * AST + c * 8);
            asm volatile("cp.async.cg.shared.global [%0], [%1], 16;\n" :: "r"(sq), "l"(gq));
        }
        issueKV(0, cs0);
        asm volatile("cp.async.commit_group;\n");
    }
    if (n_chunks > 1) {
        issueKV(1, cs0 + 64);
        asm volatile("cp.async.commit_group;\n");
    }

    int iq0 = i0 + rbase + g;
    int iq1 = iq0 + 8;

    float m0 = -1e30f, m1 = -1e30f, l0 = 0.f, l1 = 0.f;
    float oacc[8][4];
#pragma unroll
    for (int nt = 0; nt < 8; nt++)
#pragma unroll
        for (int i = 0; i < 4; i++) oacc[nt][i] = 0.f;

    for (int ci = 0; ci < n_chunks; ci++) {
        int cs = cs0 + ci * 64;
        if (ci + 1 < n_chunks) asm volatile("cp.async.wait_group 1;\n" ::: "memory");
        else                   asm volatile("cp.async.wait_group 0;\n" ::: "memory");
        __syncthreads();

        unsigned shK_st = shKV + (ci & 1) * ATT_STG_BYTES;
        unsigned shV_st = shK_st + 64 * AST * 2;

        float sacc[8][4];
#pragma unroll
        for (int nt = 0; nt < 8; nt++)
#pragma unroll
            for (int i = 0; i < 4; i++) sacc[nt][i] = 0.f;

#pragma unroll
        for (int kk = 0; kk < 4; kk++) {
            int c = kk * 16;
            unsigned af[4], bf[4][4];
            ldsm_x4(af, shQ + (unsigned)(a_off + c) * 2);
#pragma unroll
            for (int p = 0; p < 4; p++)
                ldsm_x4(bf[p], shK_st + (unsigned)(b_off + p * 16 * AST + c) * 2);
#pragma unroll
            for (int nt = 0; nt < 8; nt++)
                mma_f16(sacc[nt], af, &bf[nt >> 1][(nt & 1) * 2]);
        }

        float rmax0 = -1e30f, rmax1 = -1e30f;
#pragma unroll
        for (int nt = 0; nt < 8; nt++) {
#pragma unroll
            for (int e = 0; e < 2; e++) {
                int j = cs + nt * 8 + 2 * t + e;
                if (!((j <= iq0) && (j > iq0 - WIN))) sacc[nt][e] = -1e30f;
                if (!((j <= iq1) && (j > iq1 - WIN))) sacc[nt][2 + e] = -1e30f;
                rmax0 = fmaxf(rmax0, sacc[nt][e]);
                rmax1 = fmaxf(rmax1, sacc[nt][2 + e]);
            }
        }
#pragma unroll
        for (int msk = 1; msk < 4; msk <<= 1) {
            rmax0 = fmaxf(rmax0, __shfl_xor_sync(0xffffffffu, rmax0, msk));
            rmax1 = fmaxf(rmax1, __shfl_xor_sync(0xffffffffu, rmax1, msk));
        }

        float mn0 = fmaxf(m0, rmax0);
        float mn1 = fmaxf(m1, rmax1);
        float cor0 = ex2(m0 - mn0);
        float cor1 = ex2(m1 - mn1);
        m0 = mn0; m1 = mn1;

        float rs0 = 0.f, rs1 = 0.f;
#pragma unroll
        for (int nt = 0; nt < 8; nt++) {
            float p0 = ex2(sacc[nt][0] - mn0);
            float p1 = ex2(sacc[nt][1] - mn0);
            float p2 = ex2(sacc[nt][2] - mn1);
            float p3 = ex2(sacc[nt][3] - mn1);
            rs0 += p0 + p1;
            rs1 += p2 + p3;
            int col = nt * 8 + 2 * t;
            *(__half2*)(Ps + (rbase + g) * AST + col)     = __floats2half2_rn(p0, p1);
            *(__half2*)(Ps + (rbase + g + 8) * AST + col) = __floats2half2_rn(p2, p3);
        }
#pragma unroll
        for (int msk = 1; msk < 4; msk <<= 1) {
            rs0 += __shfl_xor_sync(0xffffffffu, rs0, msk);
            rs1 += __shfl_xor_sync(0xffffffffu, rs1, msk);
        }
        l0 = l0 * cor0 + rs0;
        l1 = l1 * cor1 + rs1;
#pragma unroll
        for (int nt = 0; nt < 8; nt++) {
            oacc[nt][0] *= cor0; oacc[nt][1] *= cor0;
            oacc[nt][2] *= cor1; oacc[nt][3] *= cor1;
        }
        __syncwarp();

#pragma unroll
        for (int kk = 0; kk < 4; kk++) {
            int c = kk * 16;
            unsigned af[4], bf[4][4];
            ldsm_x4(af, shP + (unsigned)(a_off + c) * 2);
#pragma unroll
            for (int p = 0; p < 4; p++)
                ldsm_x4_trans(bf[p], shV_st + (unsigned)(vb_off + c * AST + p * 16) * 2);
#pragma unroll
            for (int nt = 0; nt < 8; nt++)
                mma_f16(oacc[nt], af, &bf[nt >> 1][(nt & 1) * 2]);
        }

        __syncthreads();
        if (ci + 2 < n_chunks) {
            issueKV(ci & 1, cs + 128);
            asm volatile("cp.async.commit_group;\n");
        }
    }

    float inv0 = 1.f / l0;
    float inv1 = 1.f / l1;
    int b = bh / NHEADS;
    int h = bh % NHEADS;
    __half* O0 = g_O + (size_t)(b * SEQ + iq0) * D_MODEL + h * HD;
    __half* O1 = g_O + (size_t)(b * SEQ + iq1) * D_MODEL + h * HD;
#pragma unroll
    for (int nt = 0; nt < 8; nt++) {
        int d = nt * 8 + 2 * t;
        *(__half2*)(O0 + d) = __floats2half2_rn(oacc[nt][0] * inv0, oacc[nt][1] * inv0);
        *(__half2*)(O1 + d) = __floats2half2_rn(oacc[nt][2] * inv1, oacc[nt][3] * inv1);
    }
}

// ---------------------------------------------------------------------------
extern "C" void kernel_launch(void* const* d_in, const int* in_sizes, int n_in,
                              void* d_out, int out_size)
{
    const float* x  = (const float*)d_in[0];
    const float* w1 = (const float*)d_in[1];
    const float* b1 = (const float*)d_in[2];
    const float* w2 = (const float*)d_in[3];
    const float* b2 = (const float*)d_in[4];
    float* out = (float*)d_out;

    const int M = BATCH * SEQ;

    __half *cx, *cw1, *cw2;
    cudaGetSymbolAddress((void**)&cx,  c_x);
    cudaGetSymbolAddress((void**)&cw1, c_w1);
    cudaGetSymbolAddress((void**)&cw2, c_w2);

    // 0) fused fp32 -> fp16 conversion (single launch)
    {
        int n4x  = M * D_MODEL / 4;
        int n4w1 = 3 * D_MODEL * D_MODEL / 4;
        int n4w2 = D_MODEL * D_MODEL / 4;
        int total = n4x + n4w1 + n4w2;
        cvt_all<<<(total + 255) / 256, 256>>>((const float4*)x, (uint2*)cx, n4x,
                                              (const float4*)w1, (uint2*)cw1, n4w1,
                                              (const float4*)w2, (uint2*)cw2, n4w2);
    }

    const int gemm_smem = 2 * NSTG * STG_BYTES;   // 110592 B

    // 1) QKV projection: persistent, 256 CTAs x 3 tiles (Q pre-scaled)
    {
        cudaFuncSetAttribute(gemm_f16<0, 3>,
                             cudaFuncAttributeMaxDynamicSharedMemorySize, gemm_smem);
        gemm_f16<0, 3><<<256, 256, gemm_smem>>>(cx, cw1, b1, nullptr,
                                                M, 3 * D_MODEL, D_MODEL);
    }

    // 2) Sliding-window attention
    {
        int smem = (64 * AST + ATT_NSTG * ATT_STG_HALVES + 64 * AST) * (int)sizeof(__half);
        cudaFuncSetAttribute(attn_mma,
                             cudaFuncAttributeMaxDynamicSharedMemorySize, smem);
        dim3 grid(SEQ / 64, BATCH * NHEADS);
        attn_mma<<<grid, 128, smem>>>();
    }

    // 3) Output projection: 256 CTAs x 1 tile (single wave)
    {
        cudaFuncSetAttribute(gemm_f16<1, 1>,
                             cudaFuncAttributeMaxDynamicSharedMemorySize, gemm_smem);
        gemm_f16<1, 1><<<256, 256, gemm_smem>>>(nullptr, cw2, b2, out,
                                                M, D_MODEL, D_MODEL);
    }
}